// round 1
// baseline (speedup 1.0000x reference)
#include <cuda_runtime.h>
#include <cuda_bf16.h>
#include <math.h>

// ---------------------------------------------------------------------------
// Problem constants
// ---------------------------------------------------------------------------
#define N_   50000
#define E_   400000
#define E2_  450000          // E + N self loops
// ND=128, ED=64, HID=128, GIN=258, CIN=320

// ---------------------------------------------------------------------------
// Static device scratch (allocation-free rule)
// ---------------------------------------------------------------------------
__device__ int   g_deg_out[N_];
__device__ int   g_deg_in[N_];
__device__ float g_xout[(size_t)N_*128];
__device__ float g_xin [(size_t)N_*128];
__device__ float g_loop[(size_t)N_*64];    // becomes loop_attr after divide
__device__ float g_xi  [(size_t)N_*258];
__device__ float g_emb [(size_t)E_*128];
__device__ float g_xl1 [(size_t)N_*256];
__device__ float g_xr1 [(size_t)N_*256];
__device__ float g_ewE1[(size_t)E_*256];
__device__ float g_ewL1[(size_t)N_*256];
__device__ float g_logit1[(size_t)E2_*2];
__device__ float g_m1  [N_*2];
__device__ float g_den1[N_*2];
__device__ float g_osum1[(size_t)N_*256];
__device__ float g_h1  [(size_t)N_*128];
__device__ float g_xl2 [(size_t)N_*128];
__device__ float g_xr2 [(size_t)N_*128];
__device__ float g_ewE2[(size_t)E_*128];
__device__ float g_ewL2[(size_t)N_*128];
__device__ float g_logit2[E2_];
__device__ float g_m2  [N_];
__device__ float g_den2[N_];
__device__ float g_osum2[(size_t)N_*128];
__device__ float g_h2  [(size_t)N_*128];
__device__ float g_Asrc[(size_t)N_*128];
__device__ float g_Bdst[(size_t)N_*128];
__device__ float g_Cea [(size_t)E_*128];
__device__ float g_Hh  [(size_t)E_*128];
__device__ float g_Tt  [(size_t)E_*64];

// ---------------------------------------------------------------------------
// Helpers
// ---------------------------------------------------------------------------
__device__ __forceinline__ void red4(float* addr, float4 v) {
    asm volatile("red.global.add.v4.f32 [%0], {%1,%2,%3,%4};"
                 :: "l"(addr), "f"(v.x), "f"(v.y), "f"(v.z), "f"(v.w) : "memory");
}

__device__ __forceinline__ void atomicMaxF(float* addr, float v) {
    if (v >= 0.f) atomicMax((int*)addr, __float_as_int(v));
    else          atomicMin((unsigned int*)addr, __float_as_uint(v));
}

// ---------------------------------------------------------------------------
// Generic tiled SGEMM: C[M,N] = act(A[M,K] @ W[K,N] + bias)
// BM=BN=64, BK=16, 256 threads, 4x4 register tile. Requires N % 64 == 0.
// ---------------------------------------------------------------------------
template<int ACT>   // 0=none, 1=relu
__global__ void sgemm_kernel(const float* __restrict__ A, const float* __restrict__ W,
                             const float* __restrict__ bias, float* __restrict__ C,
                             int M, int N, int K)
{
    const int BM = 64, BN = 64, BK = 16;
    __shared__ __align__(16) float As[BK][BM];
    __shared__ __align__(16) float Ws[BK][BN];
    int bm = blockIdx.y * BM, bn = blockIdx.x * BN;
    int tid = threadIdx.x;
    int tx = tid & 15, ty = tid >> 4;
    float acc[4][4] = {};
    for (int k0 = 0; k0 < K; k0 += BK) {
        #pragma unroll
        for (int i = 0; i < 4; i++) {
            int idx = tid + i * 256;
            int m = idx / BK, k = idx % BK;
            int gm = bm + m, gk = k0 + k;
            As[k][m] = (gm < M && gk < K) ? A[(size_t)gm * K + gk] : 0.f;
        }
        #pragma unroll
        for (int i = 0; i < 4; i++) {
            int idx = tid + i * 256;
            int k = idx / BN, n = idx % BN;
            int gk = k0 + k;
            Ws[k][n] = (gk < K) ? W[(size_t)gk * N + bn + n] : 0.f;
        }
        __syncthreads();
        #pragma unroll
        for (int k = 0; k < BK; k++) {
            float4 a4 = *reinterpret_cast<const float4*>(&As[k][ty * 4]);
            float4 w4 = *reinterpret_cast<const float4*>(&Ws[k][tx * 4]);
            float a[4] = {a4.x, a4.y, a4.z, a4.w};
            float w[4] = {w4.x, w4.y, w4.z, w4.w};
            #pragma unroll
            for (int i = 0; i < 4; i++)
                #pragma unroll
                for (int j = 0; j < 4; j++)
                    acc[i][j] += a[i] * w[j];
        }
        __syncthreads();
    }
    #pragma unroll
    for (int i = 0; i < 4; i++) {
        int gm = bm + ty * 4 + i;
        if (gm >= M) continue;
        #pragma unroll
        for (int j = 0; j < 4; j++) {
            int gn = bn + tx * 4 + j;
            float v = acc[i][j];
            if (bias) v += bias[gn];
            if (ACT == 1) v = fmaxf(v, 0.f);
            C[(size_t)gm * N + gn] = v;
        }
    }
}

// ---------------------------------------------------------------------------
// Degree counting
// ---------------------------------------------------------------------------
__global__ void k_deg(const int* __restrict__ src, const int* __restrict__ dst) {
    int e = blockIdx.x * blockDim.x + threadIdx.x;
    if (e < E_) {
        atomicAdd(&g_deg_out[src[e]], 1);
        atomicAdd(&g_deg_in[dst[e]], 1);
    }
}

// init max buffers to -1e30
__global__ void k_init_m() {
    int i = blockIdx.x * blockDim.x + threadIdx.x;
    if (i < N_ * 2) g_m1[i] = -1e30f;
    if (i < N_)     g_m2[i] = -1e30f;
}

// ---------------------------------------------------------------------------
// Scatter emb into x_out/x_in sums + edge_attr into loop sums. 1 warp / edge.
// ---------------------------------------------------------------------------
__global__ void k_scatter(const int* __restrict__ src, const int* __restrict__ dst,
                          const float* __restrict__ ea) {
    int warp = (blockIdx.x * blockDim.x + threadIdx.x) >> 5;
    int lane = threadIdx.x & 31;
    if (warp >= E_) return;
    int s = src[warp], d = dst[warp];
    float4 v = reinterpret_cast<const float4*>(g_emb + (size_t)warp * 128)[lane];
    red4(&g_xout[(size_t)s * 128 + lane * 4], v);
    red4(&g_xin [(size_t)d * 128 + lane * 4], v);
    if (lane < 16) {
        float4 a = reinterpret_cast<const float4*>(ea + (size_t)warp * 64)[lane];
        red4(&g_loop[(size_t)d * 64 + lane * 4], a);
    }
}

// ---------------------------------------------------------------------------
// Build xi = [x_out_mean, x_in_mean, node_stats]; finalize loop_attr in place.
// 1 block / node, 128 threads.
// ---------------------------------------------------------------------------
__global__ void k_build_xi(const float* __restrict__ node_stats) {
    int n = blockIdx.x;
    int c = threadIdx.x;
    float io = 1.f / fmaxf((float)g_deg_out[n], 1.f);
    float ii = 1.f / fmaxf((float)g_deg_in[n], 1.f);
    g_xi[(size_t)n * 258 + c]        = g_xout[(size_t)n * 128 + c] * io;
    g_xi[(size_t)n * 258 + 128 + c]  = g_xin [(size_t)n * 128 + c] * ii;
    if (c < 2)  g_xi[(size_t)n * 258 + 256 + c] = node_stats[(size_t)n * 2 + c];
    if (c < 64) g_loop[(size_t)n * 64 + c] *= ii;
}

// ---------------------------------------------------------------------------
// GATv2 attention logits + segment max. 1 warp / edge (incl. self loops).
// ---------------------------------------------------------------------------
template<int H>
__global__ void k_logit(const float* __restrict__ xl, const float* __restrict__ xr,
                        const float* __restrict__ ewE, const float* __restrict__ ewL,
                        const float* __restrict__ att,
                        const int* __restrict__ src, const int* __restrict__ dst,
                        float* __restrict__ logit, float* __restrict__ m)
{
    const int CH = H * 128;
    __shared__ float satt[CH];
    if (threadIdx.x < CH) satt[threadIdx.x] = att[threadIdx.x];
    __syncthreads();
    int warp = (blockIdx.x * 256 + threadIdx.x) >> 5;
    int lane = threadIdx.x & 31;
    if (warp >= E2_) return;
    int s, d; const float* ew;
    if (warp < E_) { s = src[warp]; d = dst[warp]; ew = ewE + (size_t)warp * CH; }
    else           { s = d = warp - E_;            ew = ewL + (size_t)s * CH; }
    const float* pl = xl + (size_t)s * CH;
    const float* pr = xr + (size_t)d * CH;
    float lg[H];
    #pragma unroll
    for (int h = 0; h < H; h++) {
        lg[h] = 0.f;
        #pragma unroll
        for (int i = 0; i < 4; i++) {
            int c = h * 128 + i * 32 + lane;
            float v = pl[c] + pr[c] + ew[c];
            v = (v > 0.f) ? v : 0.2f * v;
            lg[h] += v * satt[c];
        }
    }
    #pragma unroll
    for (int h = 0; h < H; h++)
        #pragma unroll
        for (int o = 16; o > 0; o >>= 1)
            lg[h] += __shfl_xor_sync(0xffffffffu, lg[h], o);
    if (lane == 0) {
        #pragma unroll
        for (int h = 0; h < H; h++) {
            logit[(size_t)warp * H + h] = lg[h];
            atomicMaxF(&m[(size_t)d * H + h], lg[h]);
        }
    }
}

// ---------------------------------------------------------------------------
// Softmax denominator + weighted aggregation. 1 warp / edge.
// ---------------------------------------------------------------------------
template<int H>
__global__ void k_agg(const float* __restrict__ logit, const float* __restrict__ m,
                      const float* __restrict__ xl,
                      const int* __restrict__ src, const int* __restrict__ dst,
                      float* __restrict__ den, float* __restrict__ osum)
{
    const int CH = H * 128;
    int warp = (blockIdx.x * 256 + threadIdx.x) >> 5;
    int lane = threadIdx.x & 31;
    if (warp >= E2_) return;
    int s, d;
    if (warp < E_) { s = src[warp]; d = dst[warp]; }
    else           { s = d = warp - E_; }
    float a[H];
    #pragma unroll
    for (int h = 0; h < H; h++)
        a[h] = expf(logit[(size_t)warp * H + h] - m[(size_t)d * H + h]);
    if (lane == 0) {
        #pragma unroll
        for (int h = 0; h < H; h++) atomicAdd(&den[(size_t)d * H + h], a[h]);
    }
    const float* pl = xl + (size_t)s * CH;
    #pragma unroll
    for (int h = 0; h < H; h++) {
        float4 v = reinterpret_cast<const float4*>(pl + h * 128)[lane];
        v.x *= a[h]; v.y *= a[h]; v.z *= a[h]; v.w *= a[h];
        red4(&osum[((size_t)d * H + h) * 128 + lane * 4], v);
    }
}

// ---------------------------------------------------------------------------
// Node finalize: head mean + bias, layernorm, elu. 1 warp / node.
// ---------------------------------------------------------------------------
template<int H>
__global__ void k_node(const float* __restrict__ osum, const float* __restrict__ den,
                       const float* __restrict__ bias,
                       const float* __restrict__ lng, const float* __restrict__ lnb,
                       float* __restrict__ out)
{
    int warp = (blockIdx.x * 256 + threadIdx.x) >> 5;
    int lane = threadIdx.x & 31;
    if (warp >= N_) return;
    int n = warp;
    float dinv[H];
    #pragma unroll
    for (int h = 0; h < H; h++)
        dinv[h] = 1.f / fmaxf(den[(size_t)n * H + h], 1e-16f);
    float v[4];
    float sum = 0.f;
    #pragma unroll
    for (int i = 0; i < 4; i++) {
        int c = i * 32 + lane;
        float o = 0.f;
        #pragma unroll
        for (int h = 0; h < H; h++)
            o += osum[((size_t)n * H + h) * 128 + c] * dinv[h];
        o = o * (1.f / H) + bias[c];
        v[i] = o;
        sum += o;
    }
    #pragma unroll
    for (int o = 16; o > 0; o >>= 1) sum += __shfl_xor_sync(0xffffffffu, sum, o);
    float mu = sum * (1.f / 128.f);
    float var = 0.f;
    #pragma unroll
    for (int i = 0; i < 4; i++) { float t = v[i] - mu; var += t * t; }
    #pragma unroll
    for (int o = 16; o > 0; o >>= 1) var += __shfl_xor_sync(0xffffffffu, var, o);
    var *= (1.f / 128.f);
    float rs = rsqrtf(var + 1e-5f);
    #pragma unroll
    for (int i = 0; i < 4; i++) {
        int c = i * 32 + lane;
        float hn = (v[i] - mu) * rs * lng[c] + lnb[c];
        hn = (hn > 0.f) ? hn : expm1f(hn);
        out[(size_t)n * 128 + c] = hn;
    }
}

// ---------------------------------------------------------------------------
// Classifier hidden: H[e,j] = relu(A[src,j] + B[dst,j] + Cea[e,j] + c1b[j])
// ---------------------------------------------------------------------------
__global__ void k_edge_hidden(const int* __restrict__ src, const int* __restrict__ dst,
                              const float* __restrict__ c1b) {
    size_t idx = (size_t)blockIdx.x * 256 + threadIdx.x;
    if (idx >= (size_t)E_ * 128) return;
    int e = (int)(idx >> 7);
    int j = (int)(idx & 127);
    int s = __ldg(&src[e]), d = __ldg(&dst[e]);
    float v = g_Asrc[(size_t)s * 128 + j] + g_Bdst[(size_t)d * 128 + j]
            + g_Cea[idx] + c1b[j];
    g_Hh[idx] = fmaxf(v, 0.f);
}

// Final: out[e] = T[e,:] . c3w + c3b. 1 warp / edge.
__global__ void k_final(const float* __restrict__ c3w, const float* __restrict__ c3b,
                        float* __restrict__ out) {
    int warp = (blockIdx.x * 256 + threadIdx.x) >> 5;
    int lane = threadIdx.x & 31;
    if (warp >= E_) return;
    float s = g_Tt[(size_t)warp * 64 + lane]      * c3w[lane]
            + g_Tt[(size_t)warp * 64 + 32 + lane] * c3w[32 + lane];
    #pragma unroll
    for (int o = 16; o > 0; o >>= 1) s += __shfl_xor_sync(0xffffffffu, s, o);
    if (lane == 0) out[warp] = s + c3b[0];
}

// ---------------------------------------------------------------------------
// Host launch
// ---------------------------------------------------------------------------
static void* sym(const void* s) { void* p = nullptr; cudaGetSymbolAddress(&p, s); return p; }

extern "C" void kernel_launch(void* const* d_in, const int* in_sizes, int n_in,
                              void* d_out, int out_size)
{
    const float* node_stats = (const float*)d_in[1];
    const int*   edge_index = (const int*)  d_in[2];
    const float* edge_attr  = (const float*)d_in[3];
    const float* epw  = (const float*)d_in[4];
    const float* epb  = (const float*)d_in[5];
    const float* g1wl = (const float*)d_in[6];
    const float* g1wr = (const float*)d_in[7];
    const float* g1we = (const float*)d_in[8];
    const float* g1att= (const float*)d_in[9];
    const float* g1b  = (const float*)d_in[10];
    const float* n1g  = (const float*)d_in[11];
    const float* n1b  = (const float*)d_in[12];
    const float* g2wl = (const float*)d_in[13];
    const float* g2wr = (const float*)d_in[14];
    const float* g2we = (const float*)d_in[15];
    const float* g2att= (const float*)d_in[16];
    const float* g2b  = (const float*)d_in[17];
    const float* n2g  = (const float*)d_in[18];
    const float* n2b  = (const float*)d_in[19];
    const float* c1w  = (const float*)d_in[20];
    const float* c1b  = (const float*)d_in[21];
    const float* c2w  = (const float*)d_in[22];
    const float* c2b  = (const float*)d_in[23];
    const float* c3w  = (const float*)d_in[24];
    const float* c3b  = (const float*)d_in[25];

    const int* src = edge_index;
    const int* dst = edge_index + E_;
    float* out = (float*)d_out;

    // device-scratch pointers (for kernels taking pointer args)
    float* p_xi   = (float*)sym(g_xi);
    float* p_emb  = (float*)sym(g_emb);
    float* p_loop = (float*)sym(g_loop);
    float* p_xl1  = (float*)sym(g_xl1);
    float* p_xr1  = (float*)sym(g_xr1);
    float* p_ewE1 = (float*)sym(g_ewE1);
    float* p_ewL1 = (float*)sym(g_ewL1);
    float* p_lg1  = (float*)sym(g_logit1);
    float* p_m1   = (float*)sym(g_m1);
    float* p_den1 = (float*)sym(g_den1);
    float* p_os1  = (float*)sym(g_osum1);
    float* p_h1   = (float*)sym(g_h1);
    float* p_xl2  = (float*)sym(g_xl2);
    float* p_xr2  = (float*)sym(g_xr2);
    float* p_ewE2 = (float*)sym(g_ewE2);
    float* p_ewL2 = (float*)sym(g_ewL2);
    float* p_lg2  = (float*)sym(g_logit2);
    float* p_m2   = (float*)sym(g_m2);
    float* p_den2 = (float*)sym(g_den2);
    float* p_os2  = (float*)sym(g_osum2);
    float* p_h2   = (float*)sym(g_h2);
    float* p_A    = (float*)sym(g_Asrc);
    float* p_B    = (float*)sym(g_Bdst);
    float* p_Cea  = (float*)sym(g_Cea);
    float* p_Hh   = (float*)sym(g_Hh);
    float* p_Tt   = (float*)sym(g_Tt);

    // ---- zero accumulators (graph memset nodes) ----
    cudaMemsetAsync(sym(g_deg_out), 0, (size_t)N_ * 4);
    cudaMemsetAsync(sym(g_deg_in),  0, (size_t)N_ * 4);
    cudaMemsetAsync(sym(g_xout),    0, (size_t)N_ * 128 * 4);
    cudaMemsetAsync(sym(g_xin),     0, (size_t)N_ * 128 * 4);
    cudaMemsetAsync(p_loop,         0, (size_t)N_ * 64 * 4);
    cudaMemsetAsync(p_den1,         0, (size_t)N_ * 2 * 4);
    cudaMemsetAsync(p_os1,          0, (size_t)N_ * 256 * 4);
    cudaMemsetAsync(p_den2,         0, (size_t)N_ * 4);
    cudaMemsetAsync(p_os2,          0, (size_t)N_ * 128 * 4);
    k_init_m<<<(N_ * 2 + 255) / 256, 256>>>();

    // ---- phase 1: edge embedding + segment means ----
    k_deg<<<(E_ + 255) / 256, 256>>>(src, dst);
    {
        dim3 g(128 / 64, (E_ + 63) / 64);
        sgemm_kernel<1><<<g, 256>>>(edge_attr, epw, epb, p_emb, E_, 128, 64);
    }
    k_scatter<<<(E_ + 7) / 8, 256>>>(src, dst, edge_attr);
    k_build_xi<<<N_, 128>>>(node_stats);

    // ---- phase 2: GAT layer 1 (heads=2) ----
    {
        dim3 gN(256 / 64, (N_ + 63) / 64);
        sgemm_kernel<0><<<gN, 256>>>(p_xi, g1wl, nullptr, p_xl1, N_, 256, 258);
        sgemm_kernel<0><<<gN, 256>>>(p_xi, g1wr, nullptr, p_xr1, N_, 256, 258);
        dim3 gE(256 / 64, (E_ + 63) / 64);
        sgemm_kernel<0><<<gE, 256>>>(edge_attr, g1we, nullptr, p_ewE1, E_, 256, 64);
        sgemm_kernel<0><<<gN, 256>>>(p_loop, g1we, nullptr, p_ewL1, N_, 256, 64);
    }
    k_logit<2><<<(E2_ + 7) / 8, 256>>>(p_xl1, p_xr1, p_ewE1, p_ewL1, g1att, src, dst, p_lg1, p_m1);
    k_agg<2><<<(E2_ + 7) / 8, 256>>>(p_lg1, p_m1, p_xl1, src, dst, p_den1, p_os1);
    k_node<2><<<(N_ + 7) / 8, 256>>>(p_os1, p_den1, g1b, n1g, n1b, p_h1);

    // ---- phase 3: GAT layer 2 (heads=1) ----
    {
        dim3 gN(128 / 64, (N_ + 63) / 64);
        sgemm_kernel<0><<<gN, 256>>>(p_h1, g2wl, nullptr, p_xl2, N_, 128, 128);
        sgemm_kernel<0><<<gN, 256>>>(p_h1, g2wr, nullptr, p_xr2, N_, 128, 128);
        dim3 gE(128 / 64, (E_ + 63) / 64);
        sgemm_kernel<0><<<gE, 256>>>(edge_attr, g2we, nullptr, p_ewE2, E_, 128, 64);
        sgemm_kernel<0><<<gN, 256>>>(p_loop, g2we, nullptr, p_ewL2, N_, 128, 64);
    }
    k_logit<1><<<(E2_ + 7) / 8, 256>>>(p_xl2, p_xr2, p_ewE2, p_ewL2, g2att, src, dst, p_lg2, p_m2);
    k_agg<1><<<(E2_ + 7) / 8, 256>>>(p_lg2, p_m2, p_xl2, src, dst, p_den2, p_os2);
    k_node<1><<<(N_ + 7) / 8, 256>>>(p_os2, p_den2, g2b, n2g, n2b, p_h2);

    // ---- phase 4: classifier (factored) ----
    {
        dim3 gN(128 / 64, (N_ + 63) / 64);
        sgemm_kernel<0><<<gN, 256>>>(p_h2, c1w,             nullptr, p_A, N_, 128, 128);
        sgemm_kernel<0><<<gN, 256>>>(p_h2, c1w + 128 * 128, nullptr, p_B, N_, 128, 128);
        dim3 gE(128 / 64, (E_ + 63) / 64);
        sgemm_kernel<0><<<gE, 256>>>(edge_attr, c1w + 256 * 128, nullptr, p_Cea, E_, 128, 64);
    }
    k_edge_hidden<<<(int)(((size_t)E_ * 128 + 255) / 256), 256>>>(src, dst, c1b);
    {
        dim3 gE(64 / 64, (E_ + 63) / 64);
        sgemm_kernel<1><<<gE, 256>>>(p_Hh, c2w, c2b, p_Tt, E_, 64, 128);
    }
    k_final<<<(E_ + 7) / 8, 256>>>(c3w, c3b, out);
}

// round 2
// speedup vs baseline: 1.4518x; 1.4518x over previous
#include <cuda_runtime.h>
#include <cuda_bf16.h>
#include <math.h>
#include <stdint.h>

// ---------------------------------------------------------------------------
// Problem constants
// ---------------------------------------------------------------------------
#define N_   50000
#define E_   400000
#define E2_  450000          // E + N self loops
// ND=128, ED=64, HID=128, GIN=258, CIN=320

// ---------------------------------------------------------------------------
// Static device scratch (allocation-free rule)
// ---------------------------------------------------------------------------
__device__ int   g_deg_out[N_];
__device__ int   g_deg_in[N_];
__device__ float g_xout[(size_t)N_*128];
__device__ float g_xin [(size_t)N_*128];
__device__ float g_loop[(size_t)N_*64];    // becomes loop_attr after divide
__device__ float g_xi  [(size_t)N_*258];
__device__ float g_emb [(size_t)E_*128];
__device__ float g_xl1 [(size_t)N_*256];
__device__ float g_xr1 [(size_t)N_*256];
__device__ float g_ewE1[(size_t)E_*256];
__device__ float g_ewL1[(size_t)N_*256];
__device__ float g_logit1[(size_t)E2_*2];
__device__ float g_m1  [N_*2];
__device__ float g_den1[N_*2];
__device__ float g_osum1[(size_t)N_*256];
__device__ float g_h1  [(size_t)N_*128];
__device__ float g_xl2 [(size_t)N_*128];
__device__ float g_xr2 [(size_t)N_*128];
__device__ float g_ewE2[(size_t)E_*128];
__device__ float g_ewL2[(size_t)N_*128];
__device__ float g_logit2[E2_];
__device__ float g_m2  [N_];
__device__ float g_den2[N_];
__device__ float g_osum2[(size_t)N_*128];
__device__ float g_h2  [(size_t)N_*128];
__device__ float g_Asrc[(size_t)N_*128];
__device__ float g_Bdst[(size_t)N_*128];
__device__ float g_Cea [(size_t)E_*128];
__device__ float g_Hh  [(size_t)E_*128];
__device__ float g_Tt  [(size_t)E_*64];

// ---------------------------------------------------------------------------
// Helpers
// ---------------------------------------------------------------------------
__device__ __forceinline__ void red4(float* addr, float4 v) {
    asm volatile("red.global.add.v4.f32 [%0], {%1,%2,%3,%4};"
                 :: "l"(addr), "f"(v.x), "f"(v.y), "f"(v.z), "f"(v.w) : "memory");
}

__device__ __forceinline__ void atomicMaxF(float* addr, float v) {
    if (v >= 0.f) atomicMax((int*)addr, __float_as_int(v));
    else          atomicMin((unsigned int*)addr, __float_as_uint(v));
}

__device__ __forceinline__ void mma_bf16(float* c, const uint32_t* a, const uint32_t* b) {
    asm volatile(
        "mma.sync.aligned.m16n8k16.row.col.f32.bf16.bf16.f32 "
        "{%0,%1,%2,%3}, {%4,%5,%6,%7}, {%8,%9}, {%0,%1,%2,%3};"
        : "+f"(c[0]), "+f"(c[1]), "+f"(c[2]), "+f"(c[3])
        : "r"(a[0]), "r"(a[1]), "r"(a[2]), "r"(a[3]), "r"(b[0]), "r"(b[1]));
}

// ---------------------------------------------------------------------------
// Tensor-core GEMM with bf16x3 error compensation.
// C[M,N] = act(A[M,K] @ W[K,N] + bias).  A, W fp32 row-major.
// BM=128, BN=64, BK=16, 256 threads (8 warps: 4 along M x 2 along N).
// A and W are split to (hi, lo) bf16 during the global->smem stage;
// per k-step: acc += Ahi*Bhi + Alo*Bhi + Ahi*Blo  (drops only ~2^-18 term).
// Requires N % 64 == 0.
// ---------------------------------------------------------------------------
template<int ACT>   // 0=none, 1=relu
__global__ void mma_gemm(const float* __restrict__ A, const float* __restrict__ W,
                         const float* __restrict__ bias, float* __restrict__ C,
                         int M, int N, int K)
{
    constexpr int BM = 128, BN = 64, BK = 16, PAD = 20;  // 40B row stride: conflict-free
    __shared__ __nv_bfloat16 Ah[BM * PAD], Al[BM * PAD];
    __shared__ __nv_bfloat16 Bh[BN * PAD], Bl[BN * PAD];

    const int bm = blockIdx.y * BM, bn = blockIdx.x * BN;
    const int tid = threadIdx.x, wid = tid >> 5, lane = tid & 31;
    const int wm = (wid & 3) * 32;       // warp row origin within block
    const int wn = (wid >> 2) * 32;      // warp col origin within block
    const int g = lane >> 2, tig = lane & 3;

    float acc[2][4][4] = {};

    for (int k0 = 0; k0 < K; k0 += BK) {
        // ---- stage A tile [BM][BK], split hi/lo ----
        #pragma unroll
        for (int i = 0; i < 8; i++) {
            int idx = tid + i * 256;
            int m = idx >> 4, k = idx & 15;
            int gm = bm + m, gk = k0 + k;
            float v = (gm < M && gk < K) ? A[(size_t)gm * K + gk] : 0.f;
            __nv_bfloat16 h = __float2bfloat16_rn(v);
            Ah[m * PAD + k] = h;
            Al[m * PAD + k] = __float2bfloat16_rn(v - __bfloat162float(h));
        }
        // ---- stage W tile [BK][BN] transposed to [BN][BK], split hi/lo ----
        #pragma unroll
        for (int i = 0; i < 4; i++) {
            int idx = tid + i * 256;
            int k = idx >> 6, n = idx & 63;
            int gk = k0 + k;
            float v = (gk < K) ? W[(size_t)gk * N + bn + n] : 0.f;
            __nv_bfloat16 h = __float2bfloat16_rn(v);
            Bh[n * PAD + k] = h;
            Bl[n * PAD + k] = __float2bfloat16_rn(v - __bfloat162float(h));
        }
        __syncthreads();

        // ---- B fragments for this warp (4 n-tiles of 8) ----
        uint32_t bh[4][2], bl[4][2];
        #pragma unroll
        for (int nt = 0; nt < 4; nt++) {
            int n = wn + nt * 8 + g;
            bh[nt][0] = *(const uint32_t*)&Bh[n * PAD + tig * 2];
            bh[nt][1] = *(const uint32_t*)&Bh[n * PAD + tig * 2 + 8];
            bl[nt][0] = *(const uint32_t*)&Bl[n * PAD + tig * 2];
            bl[nt][1] = *(const uint32_t*)&Bl[n * PAD + tig * 2 + 8];
        }
        // ---- A fragments + MMAs (2 m-tiles of 16) ----
        #pragma unroll
        for (int mt = 0; mt < 2; mt++) {
            int r0 = wm + mt * 16 + g;
            uint32_t ah[4], al[4];
            ah[0] = *(const uint32_t*)&Ah[r0 * PAD + tig * 2];
            ah[1] = *(const uint32_t*)&Ah[(r0 + 8) * PAD + tig * 2];
            ah[2] = *(const uint32_t*)&Ah[r0 * PAD + tig * 2 + 8];
            ah[3] = *(const uint32_t*)&Ah[(r0 + 8) * PAD + tig * 2 + 8];
            al[0] = *(const uint32_t*)&Al[r0 * PAD + tig * 2];
            al[1] = *(const uint32_t*)&Al[(r0 + 8) * PAD + tig * 2];
            al[2] = *(const uint32_t*)&Al[r0 * PAD + tig * 2 + 8];
            al[3] = *(const uint32_t*)&Al[(r0 + 8) * PAD + tig * 2 + 8];
            #pragma unroll
            for (int nt = 0; nt < 4; nt++) {
                mma_bf16(acc[mt][nt], ah, bh[nt]);
                mma_bf16(acc[mt][nt], al, bh[nt]);
                mma_bf16(acc[mt][nt], ah, bl[nt]);
            }
        }
        __syncthreads();
    }

    // ---- epilogue ----
    #pragma unroll
    for (int mt = 0; mt < 2; mt++) {
        #pragma unroll
        for (int nt = 0; nt < 4; nt++) {
            int row0 = bm + wm + mt * 16 + g;
            int col0 = bn + wn + nt * 8 + tig * 2;
            #pragma unroll
            for (int half = 0; half < 2; half++) {
                int r = row0 + half * 8;
                if (r >= M) continue;
                #pragma unroll
                for (int j = 0; j < 2; j++) {
                    float v = acc[mt][nt][half * 2 + j];
                    int cidx = col0 + j;
                    if (bias) v += bias[cidx];
                    if (ACT == 1) v = fmaxf(v, 0.f);
                    C[(size_t)r * N + cidx] = v;
                }
            }
        }
    }
}

// ---------------------------------------------------------------------------
// Degree counting
// ---------------------------------------------------------------------------
__global__ void k_deg(const int* __restrict__ src, const int* __restrict__ dst) {
    int e = blockIdx.x * blockDim.x + threadIdx.x;
    if (e < E_) {
        atomicAdd(&g_deg_out[src[e]], 1);
        atomicAdd(&g_deg_in[dst[e]], 1);
    }
}

// init max buffers to -1e30
__global__ void k_init_m() {
    int i = blockIdx.x * blockDim.x + threadIdx.x;
    if (i < N_ * 2) g_m1[i] = -1e30f;
    if (i < N_)     g_m2[i] = -1e30f;
}

// ---------------------------------------------------------------------------
// Scatter emb into x_out/x_in sums + edge_attr into loop sums. 1 warp / edge.
// ---------------------------------------------------------------------------
__global__ void k_scatter(const int* __restrict__ src, const int* __restrict__ dst,
                          const float* __restrict__ ea) {
    int warp = (blockIdx.x * blockDim.x + threadIdx.x) >> 5;
    int lane = threadIdx.x & 31;
    if (warp >= E_) return;
    int s = src[warp], d = dst[warp];
    float4 v = reinterpret_cast<const float4*>(g_emb + (size_t)warp * 128)[lane];
    red4(&g_xout[(size_t)s * 128 + lane * 4], v);
    red4(&g_xin [(size_t)d * 128 + lane * 4], v);
    if (lane < 16) {
        float4 a = reinterpret_cast<const float4*>(ea + (size_t)warp * 64)[lane];
        red4(&g_loop[(size_t)d * 64 + lane * 4], a);
    }
}

// ---------------------------------------------------------------------------
// Build xi = [x_out_mean, x_in_mean, node_stats]; finalize loop_attr in place.
// ---------------------------------------------------------------------------
__global__ void k_build_xi(const float* __restrict__ node_stats) {
    int n = blockIdx.x;
    int c = threadIdx.x;
    float io = 1.f / fmaxf((float)g_deg_out[n], 1.f);
    float ii = 1.f / fmaxf((float)g_deg_in[n], 1.f);
    g_xi[(size_t)n * 258 + c]        = g_xout[(size_t)n * 128 + c] * io;
    g_xi[(size_t)n * 258 + 128 + c]  = g_xin [(size_t)n * 128 + c] * ii;
    if (c < 2)  g_xi[(size_t)n * 258 + 256 + c] = node_stats[(size_t)n * 2 + c];
    if (c < 64) g_loop[(size_t)n * 64 + c] *= ii;
}

// ---------------------------------------------------------------------------
// GATv2 attention logits + segment max. 1 warp / edge (incl. self loops).
// ---------------------------------------------------------------------------
template<int H>
__global__ void k_logit(const float* __restrict__ xl, const float* __restrict__ xr,
                        const float* __restrict__ ewE, const float* __restrict__ ewL,
                        const float* __restrict__ att,
                        const int* __restrict__ src, const int* __restrict__ dst,
                        float* __restrict__ logit, float* __restrict__ m)
{
    const int CH = H * 128;
    __shared__ float satt[CH];
    if (threadIdx.x < CH) satt[threadIdx.x] = att[threadIdx.x];
    __syncthreads();
    int warp = (blockIdx.x * 256 + threadIdx.x) >> 5;
    int lane = threadIdx.x & 31;
    if (warp >= E2_) return;
    int s, d; const float* ew;
    if (warp < E_) { s = src[warp]; d = dst[warp]; ew = ewE + (size_t)warp * CH; }
    else           { s = d = warp - E_;            ew = ewL + (size_t)s * CH; }
    const float* pl = xl + (size_t)s * CH;
    const float* pr = xr + (size_t)d * CH;
    float lg[H];
    #pragma unroll
    for (int h = 0; h < H; h++) {
        lg[h] = 0.f;
        #pragma unroll
        for (int i = 0; i < 4; i++) {
            int c = h * 128 + i * 32 + lane;
            float v = pl[c] + pr[c] + ew[c];
            v = (v > 0.f) ? v : 0.2f * v;
            lg[h] += v * satt[c];
        }
    }
    #pragma unroll
    for (int h = 0; h < H; h++)
        #pragma unroll
        for (int o = 16; o > 0; o >>= 1)
            lg[h] += __shfl_xor_sync(0xffffffffu, lg[h], o);
    if (lane == 0) {
        #pragma unroll
        for (int h = 0; h < H; h++) {
            logit[(size_t)warp * H + h] = lg[h];
            atomicMaxF(&m[(size_t)d * H + h], lg[h]);
        }
    }
}

// ---------------------------------------------------------------------------
// Softmax denominator + weighted aggregation. 1 warp / edge.
// ---------------------------------------------------------------------------
template<int H>
__global__ void k_agg(const float* __restrict__ logit, const float* __restrict__ m,
                      const float* __restrict__ xl,
                      const int* __restrict__ src, const int* __restrict__ dst,
                      float* __restrict__ den, float* __restrict__ osum)
{
    const int CH = H * 128;
    int warp = (blockIdx.x * 256 + threadIdx.x) >> 5;
    int lane = threadIdx.x & 31;
    if (warp >= E2_) return;
    int s, d;
    if (warp < E_) { s = src[warp]; d = dst[warp]; }
    else           { s = d = warp - E_; }
    float a[H];
    #pragma unroll
    for (int h = 0; h < H; h++)
        a[h] = expf(logit[(size_t)warp * H + h] - m[(size_t)d * H + h]);
    if (lane == 0) {
        #pragma unroll
        for (int h = 0; h < H; h++) atomicAdd(&den[(size_t)d * H + h], a[h]);
    }
    const float* pl = xl + (size_t)s * CH;
    #pragma unroll
    for (int h = 0; h < H; h++) {
        float4 v = reinterpret_cast<const float4*>(pl + h * 128)[lane];
        v.x *= a[h]; v.y *= a[h]; v.z *= a[h]; v.w *= a[h];
        red4(&osum[((size_t)d * H + h) * 128 + lane * 4], v);
    }
}

// ---------------------------------------------------------------------------
// Node finalize: head mean + bias, layernorm, elu. 1 warp / node.
// ---------------------------------------------------------------------------
template<int H>
__global__ void k_node(const float* __restrict__ osum, const float* __restrict__ den,
                       const float* __restrict__ bias,
                       const float* __restrict__ lng, const float* __restrict__ lnb,
                       float* __restrict__ out)
{
    int warp = (blockIdx.x * 256 + threadIdx.x) >> 5;
    int lane = threadIdx.x & 31;
    if (warp >= N_) return;
    int n = warp;
    float dinv[H];
    #pragma unroll
    for (int h = 0; h < H; h++)
        dinv[h] = 1.f / fmaxf(den[(size_t)n * H + h], 1e-16f);
    float v[4];
    float sum = 0.f;
    #pragma unroll
    for (int i = 0; i < 4; i++) {
        int c = i * 32 + lane;
        float o = 0.f;
        #pragma unroll
        for (int h = 0; h < H; h++)
            o += osum[((size_t)n * H + h) * 128 + c] * dinv[h];
        o = o * (1.f / H) + bias[c];
        v[i] = o;
        sum += o;
    }
    #pragma unroll
    for (int o = 16; o > 0; o >>= 1) sum += __shfl_xor_sync(0xffffffffu, sum, o);
    float mu = sum * (1.f / 128.f);
    float var = 0.f;
    #pragma unroll
    for (int i = 0; i < 4; i++) { float t = v[i] - mu; var += t * t; }
    #pragma unroll
    for (int o = 16; o > 0; o >>= 1) var += __shfl_xor_sync(0xffffffffu, var, o);
    var *= (1.f / 128.f);
    float rs = rsqrtf(var + 1e-5f);
    #pragma unroll
    for (int i = 0; i < 4; i++) {
        int c = i * 32 + lane;
        float hn = (v[i] - mu) * rs * lng[c] + lnb[c];
        hn = (hn > 0.f) ? hn : expm1f(hn);
        out[(size_t)n * 128 + c] = hn;
    }
}

// ---------------------------------------------------------------------------
// Classifier hidden: H[e,j] = relu(A[src,j] + B[dst,j] + Cea[e,j] + c1b[j])
// ---------------------------------------------------------------------------
__global__ void k_edge_hidden(const int* __restrict__ src, const int* __restrict__ dst,
                              const float* __restrict__ c1b) {
    size_t idx = (size_t)blockIdx.x * 256 + threadIdx.x;
    if (idx >= (size_t)E_ * 128) return;
    int e = (int)(idx >> 7);
    int j = (int)(idx & 127);
    int s = __ldg(&src[e]), d = __ldg(&dst[e]);
    float v = g_Asrc[(size_t)s * 128 + j] + g_Bdst[(size_t)d * 128 + j]
            + g_Cea[idx] + c1b[j];
    g_Hh[idx] = fmaxf(v, 0.f);
}

// Final: out[e] = T[e,:] . c3w + c3b. 1 warp / edge.
__global__ void k_final(const float* __restrict__ c3w, const float* __restrict__ c3b,
                        float* __restrict__ out) {
    int warp = (blockIdx.x * 256 + threadIdx.x) >> 5;
    int lane = threadIdx.x & 31;
    if (warp >= E_) return;
    float s = g_Tt[(size_t)warp * 64 + lane]      * c3w[lane]
            + g_Tt[(size_t)warp * 64 + 32 + lane] * c3w[32 + lane];
    #pragma unroll
    for (int o = 16; o > 0; o >>= 1) s += __shfl_xor_sync(0xffffffffu, s, o);
    if (lane == 0) out[warp] = s + c3b[0];
}

// ---------------------------------------------------------------------------
// Host launch
// ---------------------------------------------------------------------------
static void* sym(const void* s) { void* p = nullptr; cudaGetSymbolAddress(&p, s); return p; }

static inline dim3 ggrid(int M, int N) { return dim3((N + 63) / 64, (M + 127) / 128); }

extern "C" void kernel_launch(void* const* d_in, const int* in_sizes, int n_in,
                              void* d_out, int out_size)
{
    const float* node_stats = (const float*)d_in[1];
    const int*   edge_index = (const int*)  d_in[2];
    const float* edge_attr  = (const float*)d_in[3];
    const float* epw  = (const float*)d_in[4];
    const float* epb  = (const float*)d_in[5];
    const float* g1wl = (const float*)d_in[6];
    const float* g1wr = (const float*)d_in[7];
    const float* g1we = (const float*)d_in[8];
    const float* g1att= (const float*)d_in[9];
    const float* g1b  = (const float*)d_in[10];
    const float* n1g  = (const float*)d_in[11];
    const float* n1b  = (const float*)d_in[12];
    const float* g2wl = (const float*)d_in[13];
    const float* g2wr = (const float*)d_in[14];
    const float* g2we = (const float*)d_in[15];
    const float* g2att= (const float*)d_in[16];
    const float* g2b  = (const float*)d_in[17];
    const float* n2g  = (const float*)d_in[18];
    const float* n2b  = (const float*)d_in[19];
    const float* c1w  = (const float*)d_in[20];
    const float* c1b  = (const float*)d_in[21];
    const float* c2w  = (const float*)d_in[22];
    const float* c2b  = (const float*)d_in[23];
    const float* c3w  = (const float*)d_in[24];
    const float* c3b  = (const float*)d_in[25];

    const int* src = edge_index;
    const int* dst = edge_index + E_;
    float* out = (float*)d_out;

    float* p_xi   = (float*)sym(g_xi);
    float* p_emb  = (float*)sym(g_emb);
    float* p_loop = (float*)sym(g_loop);
    float* p_xl1  = (float*)sym(g_xl1);
    float* p_xr1  = (float*)sym(g_xr1);
    float* p_ewE1 = (float*)sym(g_ewE1);
    float* p_ewL1 = (float*)sym(g_ewL1);
    float* p_lg1  = (float*)sym(g_logit1);
    float* p_m1   = (float*)sym(g_m1);
    float* p_den1 = (float*)sym(g_den1);
    float* p_os1  = (float*)sym(g_osum1);
    float* p_h1   = (float*)sym(g_h1);
    float* p_xl2  = (float*)sym(g_xl2);
    float* p_xr2  = (float*)sym(g_xr2);
    float* p_ewE2 = (float*)sym(g_ewE2);
    float* p_ewL2 = (float*)sym(g_ewL2);
    float* p_lg2  = (float*)sym(g_logit2);
    float* p_m2   = (float*)sym(g_m2);
    float* p_den2 = (float*)sym(g_den2);
    float* p_os2  = (float*)sym(g_osum2);
    float* p_h2   = (float*)sym(g_h2);
    float* p_A    = (float*)sym(g_Asrc);
    float* p_B    = (float*)sym(g_Bdst);
    float* p_Cea  = (float*)sym(g_Cea);
    float* p_Hh   = (float*)sym(g_Hh);
    float* p_Tt   = (float*)sym(g_Tt);

    // ---- zero accumulators ----
    cudaMemsetAsync(sym(g_deg_out), 0, (size_t)N_ * 4);
    cudaMemsetAsync(sym(g_deg_in),  0, (size_t)N_ * 4);
    cudaMemsetAsync(sym(g_xout),    0, (size_t)N_ * 128 * 4);
    cudaMemsetAsync(sym(g_xin),     0, (size_t)N_ * 128 * 4);
    cudaMemsetAsync(p_loop,         0, (size_t)N_ * 64 * 4);
    cudaMemsetAsync(p_den1,         0, (size_t)N_ * 2 * 4);
    cudaMemsetAsync(p_os1,          0, (size_t)N_ * 256 * 4);
    cudaMemsetAsync(p_den2,         0, (size_t)N_ * 4);
    cudaMemsetAsync(p_os2,          0, (size_t)N_ * 128 * 4);
    k_init_m<<<(N_ * 2 + 255) / 256, 256>>>();

    // ---- phase 1: edge embedding + segment means ----
    k_deg<<<(E_ + 255) / 256, 256>>>(src, dst);
    mma_gemm<1><<<ggrid(E_, 128), 256>>>(edge_attr, epw, epb, p_emb, E_, 128, 64);
    k_scatter<<<(E_ + 7) / 8, 256>>>(src, dst, edge_attr);
    k_build_xi<<<N_, 128>>>(node_stats);

    // ---- phase 2: GAT layer 1 (heads=2) ----
    mma_gemm<0><<<ggrid(N_, 256), 256>>>(p_xi, g1wl, nullptr, p_xl1, N_, 256, 258);
    mma_gemm<0><<<ggrid(N_, 256), 256>>>(p_xi, g1wr, nullptr, p_xr1, N_, 256, 258);
    mma_gemm<0><<<ggrid(E_, 256), 256>>>(edge_attr, g1we, nullptr, p_ewE1, E_, 256, 64);
    mma_gemm<0><<<ggrid(N_, 256), 256>>>(p_loop, g1we, nullptr, p_ewL1, N_, 256, 64);
    k_logit<2><<<(E2_ + 7) / 8, 256>>>(p_xl1, p_xr1, p_ewE1, p_ewL1, g1att, src, dst, p_lg1, p_m1);
    k_agg<2><<<(E2_ + 7) / 8, 256>>>(p_lg1, p_m1, p_xl1, src, dst, p_den1, p_os1);
    k_node<2><<<(N_ + 7) / 8, 256>>>(p_os1, p_den1, g1b, n1g, n1b, p_h1);

    // ---- phase 3: GAT layer 2 (heads=1) ----
    mma_gemm<0><<<ggrid(N_, 128), 256>>>(p_h1, g2wl, nullptr, p_xl2, N_, 128, 128);
    mma_gemm<0><<<ggrid(N_, 128), 256>>>(p_h1, g2wr, nullptr, p_xr2, N_, 128, 128);
    mma_gemm<0><<<ggrid(E_, 128), 256>>>(edge_attr, g2we, nullptr, p_ewE2, E_, 128, 64);
    mma_gemm<0><<<ggrid(N_, 128), 256>>>(p_loop, g2we, nullptr, p_ewL2, N_, 128, 64);
    k_logit<1><<<(E2_ + 7) / 8, 256>>>(p_xl2, p_xr2, p_ewE2, p_ewL2, g2att, src, dst, p_lg2, p_m2);
    k_agg<1><<<(E2_ + 7) / 8, 256>>>(p_lg2, p_m2, p_xl2, src, dst, p_den2, p_os2);
    k_node<1><<<(N_ + 7) / 8, 256>>>(p_os2, p_den2, g2b, n2g, n2b, p_h2);

    // ---- phase 4: classifier (factored) ----
    mma_gemm<0><<<ggrid(N_, 128), 256>>>(p_h2, c1w,             nullptr, p_A, N_, 128, 128);
    mma_gemm<0><<<ggrid(N_, 128), 256>>>(p_h2, c1w + 128 * 128, nullptr, p_B, N_, 128, 128);
    mma_gemm<0><<<ggrid(E_, 128), 256>>>(edge_attr, c1w + 256 * 128, nullptr, p_Cea, E_, 128, 64);
    k_edge_hidden<<<(int)(((size_t)E_ * 128 + 255) / 256), 256>>>(src, dst, c1b);
    mma_gemm<1><<<ggrid(E_, 64), 256>>>(p_Hh, c2w, c2b, p_Tt, E_, 64, 128);
    k_final<<<(E_ + 7) / 8, 256>>>(c3w, c3b, out);
}

// round 3
// speedup vs baseline: 1.7863x; 1.2304x over previous
#include <cuda_runtime.h>
#include <cuda_bf16.h>
#include <math.h>
#include <stdint.h>

// ---------------------------------------------------------------------------
// Problem constants
// ---------------------------------------------------------------------------
#define N_   50000
#define E_   400000
#define E2_  450000          // E + N self loops
// ND=128, ED=64, HID=128, GIN=258, CIN=320

// ---------------------------------------------------------------------------
// Static device scratch
// ---------------------------------------------------------------------------
__device__ int   g_deg_out[N_];
__device__ int   g_deg_in[N_];
__device__ float g_xout[(size_t)N_*128];
__device__ float g_xin [(size_t)N_*128];
__device__ float g_loop[(size_t)N_*64];
__device__ float g_xi  [(size_t)N_*258];
__device__ float g_xl1 [(size_t)N_*256];
__device__ float g_xr1 [(size_t)N_*256];
__device__ float g_ewE1[(size_t)E_*256];
__device__ float g_ewL1[(size_t)N_*256];
__device__ float g_den1[N_*2];
__device__ float g_osum1[(size_t)N_*256];
__device__ float g_h1  [(size_t)N_*128];
__device__ float g_xl2 [(size_t)N_*128];
__device__ float g_xr2 [(size_t)N_*128];
__device__ float g_ewE2[(size_t)E_*128];
__device__ float g_ewL2[(size_t)N_*128];
__device__ float g_den2[N_];
__device__ float g_osum2[(size_t)N_*128];
__device__ float g_h2  [(size_t)N_*128];
__device__ float g_Asrc[(size_t)N_*128];
__device__ float g_Bdst[(size_t)N_*128];
__device__ float g_Cea [(size_t)E_*128];

// ---------------------------------------------------------------------------
// Helpers
// ---------------------------------------------------------------------------
__device__ __forceinline__ void red4(float* addr, float4 v) {
    asm volatile("red.global.add.v4.f32 [%0], {%1,%2,%3,%4};"
                 :: "l"(addr), "f"(v.x), "f"(v.y), "f"(v.z), "f"(v.w) : "memory");
}
__device__ __forceinline__ void red2(float* addr, float a, float b) {
    asm volatile("red.global.add.v2.f32 [%0], {%1,%2};"
                 :: "l"(addr), "f"(a), "f"(b) : "memory");
}

__device__ __forceinline__ void mma_bf16(float* c, const uint32_t* a, const uint32_t* b) {
    asm volatile(
        "mma.sync.aligned.m16n8k16.row.col.f32.bf16.bf16.f32 "
        "{%0,%1,%2,%3}, {%4,%5,%6,%7}, {%8,%9}, {%0,%1,%2,%3};"
        : "+f"(c[0]), "+f"(c[1]), "+f"(c[2]), "+f"(c[3])
        : "r"(a[0]), "r"(a[1]), "r"(a[2]), "r"(a[3]), "r"(b[0]), "r"(b[1]));
}

__device__ __forceinline__ void split_bf16(float v, __nv_bfloat16& h, __nv_bfloat16& l) {
    h = __float2bfloat16_rn(v);
    l = __float2bfloat16_rn(v - __bfloat162float(h));
}

// ---------------------------------------------------------------------------
// Tensor-core GEMM, bf16x3 compensated. C = act(A[M,K]@W[K,N] + bias).
// BM=128, BN=128, BK=16, 256 threads (8 warps: 4M x 2N).
// EPI: 0 = store, 1 = relu+store, 2 = relu + red.v2 scatter into
//      g_xout[src[row]] and g_xin[dst[row]] (requires N == 128, exact M tiles).
// ---------------------------------------------------------------------------
template<int EPI>
__global__ void mma_gemm(const float* __restrict__ A, const float* __restrict__ W,
                         const float* __restrict__ bias, float* __restrict__ C,
                         int M, int N, int K,
                         const int* __restrict__ src, const int* __restrict__ dst)
{
    constexpr int BM = 128, BN = 128, BK = 16, PAD = 20;
    __shared__ __nv_bfloat16 Ah[BM * PAD], Al[BM * PAD];
    __shared__ __nv_bfloat16 Bh[BN * PAD], Bl[BN * PAD];

    const int bm = blockIdx.y * BM, bn = blockIdx.x * BN;
    const int tid = threadIdx.x, wid = tid >> 5, lane = tid & 31;
    const int wm = (wid & 3) * 32;
    const int wn = (wid >> 2) * 64;
    const int g = lane >> 2, tig = lane & 3;

    float acc[2][8][4] = {};

    for (int k0 = 0; k0 < K; k0 += BK) {
        #pragma unroll
        for (int i = 0; i < 8; i++) {
            int idx = tid + i * 256;
            int m = idx >> 4, k = idx & 15;
            int gm = bm + m, gk = k0 + k;
            float v = (gm < M && gk < K) ? A[(size_t)gm * K + gk] : 0.f;
            split_bf16(v, Ah[m * PAD + k], Al[m * PAD + k]);
        }
        #pragma unroll
        for (int i = 0; i < 8; i++) {
            int idx = tid + i * 256;
            int k = idx >> 7, n = idx & 127;
            int gk = k0 + k;
            float v = (gk < K) ? W[(size_t)gk * N + bn + n] : 0.f;
            split_bf16(v, Bh[n * PAD + k], Bl[n * PAD + k]);
        }
        __syncthreads();

        uint32_t bh[8][2], bl[8][2];
        #pragma unroll
        for (int nt = 0; nt < 8; nt++) {
            int n = wn + nt * 8 + g;
            bh[nt][0] = *(const uint32_t*)&Bh[n * PAD + tig * 2];
            bh[nt][1] = *(const uint32_t*)&Bh[n * PAD + tig * 2 + 8];
            bl[nt][0] = *(const uint32_t*)&Bl[n * PAD + tig * 2];
            bl[nt][1] = *(const uint32_t*)&Bl[n * PAD + tig * 2 + 8];
        }
        #pragma unroll
        for (int mt = 0; mt < 2; mt++) {
            int r0 = wm + mt * 16 + g;
            uint32_t ah[4], al[4];
            ah[0] = *(const uint32_t*)&Ah[r0 * PAD + tig * 2];
            ah[1] = *(const uint32_t*)&Ah[(r0 + 8) * PAD + tig * 2];
            ah[2] = *(const uint32_t*)&Ah[r0 * PAD + tig * 2 + 8];
            ah[3] = *(const uint32_t*)&Ah[(r0 + 8) * PAD + tig * 2 + 8];
            al[0] = *(const uint32_t*)&Al[r0 * PAD + tig * 2];
            al[1] = *(const uint32_t*)&Al[(r0 + 8) * PAD + tig * 2];
            al[2] = *(const uint32_t*)&Al[r0 * PAD + tig * 2 + 8];
            al[3] = *(const uint32_t*)&Al[(r0 + 8) * PAD + tig * 2 + 8];
            #pragma unroll
            for (int nt = 0; nt < 8; nt++) {
                mma_bf16(acc[mt][nt], ah, bh[nt]);
                mma_bf16(acc[mt][nt], al, bh[nt]);
                mma_bf16(acc[mt][nt], ah, bl[nt]);
            }
        }
        __syncthreads();
    }

    #pragma unroll
    for (int mt = 0; mt < 2; mt++) {
        #pragma unroll
        for (int half = 0; half < 2; half++) {
            int r = bm + wm + mt * 16 + g + half * 8;
            if (r >= M) continue;
            int s = 0, d = 0;
            if (EPI == 2) { s = src[r]; d = dst[r]; }
            #pragma unroll
            for (int nt = 0; nt < 8; nt++) {
                int col0 = bn + wn + nt * 8 + tig * 2;
                float v0 = acc[mt][nt][half * 2 + 0];
                float v1 = acc[mt][nt][half * 2 + 1];
                if (bias) { v0 += bias[col0]; v1 += bias[col0 + 1]; }
                if (EPI >= 1) { v0 = fmaxf(v0, 0.f); v1 = fmaxf(v1, 0.f); }
                if (EPI == 2) {
                    red2(&g_xout[(size_t)s * 128 + col0], v0, v1);
                    red2(&g_xin [(size_t)d * 128 + col0], v0, v1);
                } else {
                    *(float2*)&C[(size_t)r * N + col0] = make_float2(v0, v1);
                }
            }
        }
    }
}

// ---------------------------------------------------------------------------
// Degrees + loop_attr sum. 1 warp / edge.
// ---------------------------------------------------------------------------
__global__ void k_deg_loop(const int* __restrict__ src, const int* __restrict__ dst,
                           const float* __restrict__ ea) {
    int warp = (blockIdx.x * 256 + threadIdx.x) >> 5;
    int lane = threadIdx.x & 31;
    if (warp >= E_) return;
    int s = src[warp], d = dst[warp];
    if (lane == 0) atomicAdd(&g_deg_out[s], 1);
    if (lane == 1) atomicAdd(&g_deg_in[d], 1);
    if (lane < 16) {
        float4 a = reinterpret_cast<const float4*>(ea + (size_t)warp * 64)[lane];
        red4(&g_loop[(size_t)d * 64 + lane * 4], a);
    }
}

// ---------------------------------------------------------------------------
// Build xi; finalize loop_attr.
// ---------------------------------------------------------------------------
__global__ void k_build_xi(const float* __restrict__ node_stats) {
    int n = blockIdx.x;
    int c = threadIdx.x;
    float io = 1.f / fmaxf((float)g_deg_out[n], 1.f);
    float ii = 1.f / fmaxf((float)g_deg_in[n], 1.f);
    g_xi[(size_t)n * 258 + c]        = g_xout[(size_t)n * 128 + c] * io;
    g_xi[(size_t)n * 258 + 128 + c]  = g_xin [(size_t)n * 128 + c] * ii;
    if (c < 2)  g_xi[(size_t)n * 258 + 256 + c] = node_stats[(size_t)n * 2 + c];
    if (c < 64) g_loop[(size_t)n * 64 + c] *= ii;
}

// ---------------------------------------------------------------------------
// Fused GATv2 attention: logit + exp (no max shift; logits are O(1)) +
// denominator + weighted scatter, single pass. 1 warp / edge.
// ---------------------------------------------------------------------------
template<int H>
__global__ void k_attn(const float* __restrict__ xl, const float* __restrict__ xr,
                       const float* __restrict__ ewE, const float* __restrict__ ewL,
                       const float* __restrict__ att,
                       const int* __restrict__ src, const int* __restrict__ dst,
                       float* __restrict__ den, float* __restrict__ osum)
{
    const int CH = H * 128;
    __shared__ float satt[CH];
    if (threadIdx.x < CH) satt[threadIdx.x] = att[threadIdx.x];
    __syncthreads();
    int warp = (blockIdx.x * 256 + threadIdx.x) >> 5;
    int lane = threadIdx.x & 31;
    if (warp >= E2_) return;
    int s, d; const float* ew;
    if (warp < E_) { s = src[warp]; d = dst[warp]; ew = ewE + (size_t)warp * CH; }
    else           { s = d = warp - E_;            ew = ewL + (size_t)s * CH; }
    const float* pl = xl + (size_t)s * CH;
    const float* pr = xr + (size_t)d * CH;

    float4 xlv[H];
    float lg[H];
    #pragma unroll
    for (int h = 0; h < H; h++) {
        int off = h * 128 + lane * 4;
        float4 l4 = *(const float4*)&pl[off];
        float4 r4 = *(const float4*)&pr[off];
        float4 e4 = *(const float4*)&ew[off];
        float4 a4 = *(const float4*)&satt[off];
        xlv[h] = l4;
        float v0 = l4.x + r4.x + e4.x; v0 = (v0 > 0.f) ? v0 : 0.2f * v0;
        float v1 = l4.y + r4.y + e4.y; v1 = (v1 > 0.f) ? v1 : 0.2f * v1;
        float v2 = l4.z + r4.z + e4.z; v2 = (v2 > 0.f) ? v2 : 0.2f * v2;
        float v3 = l4.w + r4.w + e4.w; v3 = (v3 > 0.f) ? v3 : 0.2f * v3;
        lg[h] = v0 * a4.x + v1 * a4.y + v2 * a4.z + v3 * a4.w;
    }
    #pragma unroll
    for (int h = 0; h < H; h++)
        #pragma unroll
        for (int o = 16; o > 0; o >>= 1)
            lg[h] += __shfl_xor_sync(0xffffffffu, lg[h], o);
    float a[H];
    #pragma unroll
    for (int h = 0; h < H; h++) a[h] = expf(lg[h]);
    if (lane == 0) {
        #pragma unroll
        for (int h = 0; h < H; h++) atomicAdd(&den[(size_t)d * H + h], a[h]);
    }
    #pragma unroll
    for (int h = 0; h < H; h++) {
        float4 v = xlv[h];
        v.x *= a[h]; v.y *= a[h]; v.z *= a[h]; v.w *= a[h];
        red4(&osum[((size_t)d * H + h) * 128 + lane * 4], v);
    }
}

// ---------------------------------------------------------------------------
// Node finalize: head mean + bias, layernorm, elu. 1 warp / node.
// ---------------------------------------------------------------------------
template<int H>
__global__ void k_node(const float* __restrict__ osum, const float* __restrict__ den,
                       const float* __restrict__ bias,
                       const float* __restrict__ lng, const float* __restrict__ lnb,
                       float* __restrict__ out)
{
    int warp = (blockIdx.x * 256 + threadIdx.x) >> 5;
    int lane = threadIdx.x & 31;
    if (warp >= N_) return;
    int n = warp;
    float dinv[H];
    #pragma unroll
    for (int h = 0; h < H; h++)
        dinv[h] = 1.f / fmaxf(den[(size_t)n * H + h], 1e-16f);
    float v[4];
    float sum = 0.f;
    #pragma unroll
    for (int i = 0; i < 4; i++) {
        int c = i * 32 + lane;
        float o = 0.f;
        #pragma unroll
        for (int h = 0; h < H; h++)
            o += osum[((size_t)n * H + h) * 128 + c] * dinv[h];
        o = o * (1.f / H) + bias[c];
        v[i] = o;
        sum += o;
    }
    #pragma unroll
    for (int o = 16; o > 0; o >>= 1) sum += __shfl_xor_sync(0xffffffffu, sum, o);
    float mu = sum * (1.f / 128.f);
    float var = 0.f;
    #pragma unroll
    for (int i = 0; i < 4; i++) { float t = v[i] - mu; var += t * t; }
    #pragma unroll
    for (int o = 16; o > 0; o >>= 1) var += __shfl_xor_sync(0xffffffffu, var, o);
    var *= (1.f / 128.f);
    float rs = rsqrtf(var + 1e-5f);
    #pragma unroll
    for (int i = 0; i < 4; i++) {
        int c = i * 32 + lane;
        float hn = (v[i] - mu) * rs * lng[c] + lnb[c];
        hn = (hn > 0.f) ? hn : expm1f(hn);
        out[(size_t)n * 128 + c] = hn;
    }
}

// ---------------------------------------------------------------------------
// Fused classifier: per-edge h = relu(A[src]+B[dst]+Cea+c1b) built in smem,
// tensor-core h@c2w (K=128 -> N=64), epilogue relu + dot with c3w, row-reduce.
// 128 edges / block, 256 threads.
// ---------------------------------------------------------------------------
__global__ void k_classifier(const int* __restrict__ src, const int* __restrict__ dst,
                             const float* __restrict__ c1b, const float* __restrict__ c2w,
                             const float* __restrict__ c2b, const float* __restrict__ c3w,
                             const float* __restrict__ c3b, float* __restrict__ out)
{
    constexpr int BM = 128, BN = 64, BK = 16, PAD = 20, K = 128;
    __shared__ __nv_bfloat16 Ah[BM * PAD], Al[BM * PAD];
    __shared__ __nv_bfloat16 Bh[BN * PAD], Bl[BN * PAD];
    __shared__ int ssrc[BM], sdst[BM];
    __shared__ float rowsum[BM];

    const int bm = blockIdx.x * BM;
    const int tid = threadIdx.x, wid = tid >> 5, lane = tid & 31;
    const int wm = (wid & 3) * 32;
    const int wn = (wid >> 2) * 32;
    const int g = lane >> 2, tig = lane & 3;

    if (tid < BM) {
        ssrc[tid] = src[bm + tid];
        sdst[tid] = dst[bm + tid];
        rowsum[tid] = 0.f;
    }
    __syncthreads();

    float acc[2][4][4] = {};

    for (int k0 = 0; k0 < K; k0 += BK) {
        #pragma unroll
        for (int i = 0; i < 8; i++) {
            int idx = tid + i * 256;
            int m = idx >> 4, k = idx & 15;
            int e = bm + m, gk = k0 + k;
            float v = g_Asrc[(size_t)ssrc[m] * 128 + gk]
                    + g_Bdst[(size_t)sdst[m] * 128 + gk]
                    + g_Cea[(size_t)e * 128 + gk] + c1b[gk];
            v = fmaxf(v, 0.f);
            split_bf16(v, Ah[m * PAD + k], Al[m * PAD + k]);
        }
        #pragma unroll
        for (int i = 0; i < 4; i++) {
            int idx = tid + i * 256;
            int k = idx >> 6, n = idx & 63;
            float v = c2w[(size_t)(k0 + k) * 64 + n];
            split_bf16(v, Bh[n * PAD + k], Bl[n * PAD + k]);
        }
        __syncthreads();

        uint32_t bh[4][2], bl[4][2];
        #pragma unroll
        for (int nt = 0; nt < 4; nt++) {
            int n = wn + nt * 8 + g;
            bh[nt][0] = *(const uint32_t*)&Bh[n * PAD + tig * 2];
            bh[nt][1] = *(const uint32_t*)&Bh[n * PAD + tig * 2 + 8];
            bl[nt][0] = *(const uint32_t*)&Bl[n * PAD + tig * 2];
            bl[nt][1] = *(const uint32_t*)&Bl[n * PAD + tig * 2 + 8];
        }
        #pragma unroll
        for (int mt = 0; mt < 2; mt++) {
            int r0 = wm + mt * 16 + g;
            uint32_t ah[4], al[4];
            ah[0] = *(const uint32_t*)&Ah[r0 * PAD + tig * 2];
            ah[1] = *(const uint32_t*)&Ah[(r0 + 8) * PAD + tig * 2];
            ah[2] = *(const uint32_t*)&Ah[r0 * PAD + tig * 2 + 8];
            ah[3] = *(const uint32_t*)&Ah[(r0 + 8) * PAD + tig * 2 + 8];
            al[0] = *(const uint32_t*)&Al[r0 * PAD + tig * 2];
            al[1] = *(const uint32_t*)&Al[(r0 + 8) * PAD + tig * 2];
            al[2] = *(const uint32_t*)&Al[r0 * PAD + tig * 2 + 8];
            al[3] = *(const uint32_t*)&Al[(r0 + 8) * PAD + tig * 2 + 8];
            #pragma unroll
            for (int nt = 0; nt < 4; nt++) {
                mma_bf16(acc[mt][nt], ah, bh[nt]);
                mma_bf16(acc[mt][nt], al, bh[nt]);
                mma_bf16(acc[mt][nt], ah, bl[nt]);
            }
        }
        __syncthreads();
    }

    // epilogue: relu(t + c2b) . c3w, reduce per row
    #pragma unroll
    for (int mt = 0; mt < 2; mt++) {
        #pragma unroll
        for (int half = 0; half < 2; half++) {
            int r = wm + mt * 16 + g + half * 8;
            float p = 0.f;
            #pragma unroll
            for (int nt = 0; nt < 4; nt++) {
                int col = wn + nt * 8 + tig * 2;
                float t0 = fmaxf(acc[mt][nt][half * 2 + 0] + c2b[col], 0.f);
                float t1 = fmaxf(acc[mt][nt][half * 2 + 1] + c2b[col + 1], 0.f);
                p += t0 * c3w[col] + t1 * c3w[col + 1];
            }
            atomicAdd(&rowsum[r], p);
        }
    }
    __syncthreads();
    if (tid < BM) out[bm + tid] = rowsum[tid] + c3b[0];
}

// ---------------------------------------------------------------------------
// Host launch
// ---------------------------------------------------------------------------
static void* sym(const void* s) { void* p = nullptr; cudaGetSymbolAddress(&p, s); return p; }

static inline dim3 ggrid(int M, int N) { return dim3((N + 127) / 128, (M + 127) / 128); }

extern "C" void kernel_launch(void* const* d_in, const int* in_sizes, int n_in,
                              void* d_out, int out_size)
{
    const float* node_stats = (const float*)d_in[1];
    const int*   edge_index = (const int*)  d_in[2];
    const float* edge_attr  = (const float*)d_in[3];
    const float* epw  = (const float*)d_in[4];
    const float* epb  = (const float*)d_in[5];
    const float* g1wl = (const float*)d_in[6];
    const float* g1wr = (const float*)d_in[7];
    const float* g1we = (const float*)d_in[8];
    const float* g1att= (const float*)d_in[9];
    const float* g1b  = (const float*)d_in[10];
    const float* n1g  = (const float*)d_in[11];
    const float* n1b  = (const float*)d_in[12];
    const float* g2wl = (const float*)d_in[13];
    const float* g2wr = (const float*)d_in[14];
    const float* g2we = (const float*)d_in[15];
    const float* g2att= (const float*)d_in[16];
    const float* g2b  = (const float*)d_in[17];
    const float* n2g  = (const float*)d_in[18];
    const float* n2b  = (const float*)d_in[19];
    const float* c1w  = (const float*)d_in[20];
    const float* c1b  = (const float*)d_in[21];
    const float* c2w  = (const float*)d_in[22];
    const float* c2b  = (const float*)d_in[23];
    const float* c3w  = (const float*)d_in[24];
    const float* c3b  = (const float*)d_in[25];

    const int* src = edge_index;
    const int* dst = edge_index + E_;
    float* out = (float*)d_out;

    float* p_xi   = (float*)sym(g_xi);
    float* p_loop = (float*)sym(g_loop);
    float* p_xl1  = (float*)sym(g_xl1);
    float* p_xr1  = (float*)sym(g_xr1);
    float* p_ewE1 = (float*)sym(g_ewE1);
    float* p_ewL1 = (float*)sym(g_ewL1);
    float* p_den1 = (float*)sym(g_den1);
    float* p_os1  = (float*)sym(g_osum1);
    float* p_h1   = (float*)sym(g_h1);
    float* p_xl2  = (float*)sym(g_xl2);
    float* p_xr2  = (float*)sym(g_xr2);
    float* p_ewE2 = (float*)sym(g_ewE2);
    float* p_ewL2 = (float*)sym(g_ewL2);
    float* p_den2 = (float*)sym(g_den2);
    float* p_os2  = (float*)sym(g_osum2);
    float* p_h2   = (float*)sym(g_h2);
    float* p_A    = (float*)sym(g_Asrc);
    float* p_B    = (float*)sym(g_Bdst);
    float* p_Cea  = (float*)sym(g_Cea);

    // ---- zero accumulators ----
    cudaMemsetAsync(sym(g_deg_out), 0, (size_t)N_ * 4);
    cudaMemsetAsync(sym(g_deg_in),  0, (size_t)N_ * 4);
    cudaMemsetAsync(sym(g_xout),    0, (size_t)N_ * 128 * 4);
    cudaMemsetAsync(sym(g_xin),     0, (size_t)N_ * 128 * 4);
    cudaMemsetAsync(p_loop,         0, (size_t)N_ * 64 * 4);
    cudaMemsetAsync(p_den1,         0, (size_t)N_ * 2 * 4);
    cudaMemsetAsync(p_os1,          0, (size_t)N_ * 256 * 4);
    cudaMemsetAsync(p_den2,         0, (size_t)N_ * 4);
    cudaMemsetAsync(p_os2,          0, (size_t)N_ * 128 * 4);

    // ---- phase 1: degrees, loop sums, emb GEMM fused with mean-scatter ----
    k_deg_loop<<<(E_ + 7) / 8, 256>>>(src, dst, edge_attr);
    mma_gemm<2><<<ggrid(E_, 128), 256>>>(edge_attr, epw, epb, nullptr, E_, 128, 64, src, dst);
    k_build_xi<<<N_, 128>>>(node_stats);

    // ---- phase 2: GAT layer 1 (heads=2) ----
    mma_gemm<0><<<ggrid(N_, 256), 256>>>(p_xi, g1wl, nullptr, p_xl1, N_, 256, 258, nullptr, nullptr);
    mma_gemm<0><<<ggrid(N_, 256), 256>>>(p_xi, g1wr, nullptr, p_xr1, N_, 256, 258, nullptr, nullptr);
    mma_gemm<0><<<ggrid(E_, 256), 256>>>(edge_attr, g1we, nullptr, p_ewE1, E_, 256, 64, nullptr, nullptr);
    mma_gemm<0><<<ggrid(N_, 256), 256>>>(p_loop, g1we, nullptr, p_ewL1, N_, 256, 64, nullptr, nullptr);
    k_attn<2><<<(E2_ + 7) / 8, 256>>>(p_xl1, p_xr1, p_ewE1, p_ewL1, g1att, src, dst, p_den1, p_os1);
    k_node<2><<<(N_ + 7) / 8, 256>>>(p_os1, p_den1, g1b, n1g, n1b, p_h1);

    // ---- phase 3: GAT layer 2 (heads=1) ----
    mma_gemm<0><<<ggrid(N_, 128), 256>>>(p_h1, g2wl, nullptr, p_xl2, N_, 128, 128, nullptr, nullptr);
    mma_gemm<0><<<ggrid(N_, 128), 256>>>(p_h1, g2wr, nullptr, p_xr2, N_, 128, 128, nullptr, nullptr);
    mma_gemm<0><<<ggrid(E_, 128), 256>>>(edge_attr, g2we, nullptr, p_ewE2, E_, 128, 64, nullptr, nullptr);
    mma_gemm<0><<<ggrid(N_, 128), 256>>>(p_loop, g2we, nullptr, p_ewL2, N_, 128, 64, nullptr, nullptr);
    k_attn<1><<<(E2_ + 7) / 8, 256>>>(p_xl2, p_xr2, p_ewE2, p_ewL2, g2att, src, dst, p_den2, p_os2);
    k_node<1><<<(N_ + 7) / 8, 256>>>(p_os2, p_den2, g2b, n2g, n2b, p_h2);

    // ---- phase 4: classifier (factored + fused) ----
    mma_gemm<0><<<ggrid(N_, 128), 256>>>(p_h2, c1w,             nullptr, p_A, N_, 128, 128, nullptr, nullptr);
    mma_gemm<0><<<ggrid(N_, 128), 256>>>(p_h2, c1w + 128 * 128, nullptr, p_B, N_, 128, 128, nullptr, nullptr);
    mma_gemm<0><<<ggrid(E_, 128), 256>>>(edge_attr, c1w + 256 * 128, nullptr, p_Cea, E_, 128, 64, nullptr, nullptr);
    k_classifier<<<E_ / 128, 256>>>(src, dst, c1b, c2w, c2b, c3w, c3b, out);
}

// round 5
// speedup vs baseline: 2.0658x; 1.1565x over previous
#include <cuda_runtime.h>
#include <cuda_bf16.h>
#include <math.h>
#include <stdint.h>

// ---------------------------------------------------------------------------
// Problem constants
// ---------------------------------------------------------------------------
#define N_   50000
#define E_   400000
#define E2_  450000          // E + N self loops
// ND=128, ED=64, HID=128, GIN=258 (padded to 272), CIN=320

// ---------------------------------------------------------------------------
// Static device scratch
// ---------------------------------------------------------------------------
__device__ __align__(16) int   g_deg_out[N_];
__device__ __align__(16) int   g_deg_in[N_];
__device__ __align__(16) float g_xout[(size_t)N_*128];
__device__ __align__(16) float g_xin [(size_t)N_*128];
__device__ __align__(16) float g_loop[(size_t)N_*64];
__device__ __align__(16) float g_xi  [(size_t)N_*272];   // zero-padded 258..271
__device__ __align__(16) float g_x1  [(size_t)N_*512];   // xl1 | xr1
__device__ __align__(16) float g_ew  [(size_t)E_*512];   // ewE1(256) | ewE2(128) | Cea(128)
__device__ __align__(16) float g_ewL [(size_t)N_*384];   // ewL1(256) | ewL2(128)
__device__ __align__(16) float g_den1[N_*2];
__device__ __align__(16) float g_osum1[(size_t)N_*256];
__device__ __align__(16) float g_h1  [(size_t)N_*128];
__device__ __align__(16) float g_x2  [(size_t)N_*256];   // xl2 | xr2
__device__ __align__(16) float g_den2[N_];
__device__ __align__(16) float g_osum2[(size_t)N_*128];
__device__ __align__(16) float g_h2  [(size_t)N_*128];
__device__ __align__(16) float g_AB  [(size_t)N_*256];   // Asrc | Bdst

// packed weights: [n][kpad/2] uint32 (bf16x2 pairs along k)
__device__ __align__(16) uint32_t wp_W1h[512*136], wp_W1l[512*136];   // g1wl|g1wr, kpad=272
__device__ __align__(16) uint32_t wp_Weh[512*32],  wp_Wel[512*32];    // g1we|g2we|c1w_e, kpad=64
__device__ __align__(16) uint32_t wp_W2h[256*64],  wp_W2l[256*64];    // g2wl|g2wr, kpad=128
__device__ __align__(16) uint32_t wp_ABh[256*64],  wp_ABl[256*64];    // c1w_a|c1w_b, kpad=128
__device__ __align__(16) uint32_t wp_Ebh[128*32],  wp_Ebl[128*32];    // epw, kpad=64

// ---------------------------------------------------------------------------
// Helpers
// ---------------------------------------------------------------------------
__device__ __forceinline__ void red4(float* addr, float4 v) {
    asm volatile("red.global.add.v4.f32 [%0], {%1,%2,%3,%4};"
                 :: "l"(addr), "f"(v.x), "f"(v.y), "f"(v.z), "f"(v.w) : "memory");
}
__device__ __forceinline__ void red2(float* addr, float a, float b) {
    asm volatile("red.global.add.v2.f32 [%0], {%1,%2};"
                 :: "l"(addr), "f"(a), "f"(b) : "memory");
}

__device__ __forceinline__ void mma_bf16(float* c, const uint32_t* a, const uint32_t* b) {
    asm volatile(
        "mma.sync.aligned.m16n8k16.row.col.f32.bf16.bf16.f32 "
        "{%0,%1,%2,%3}, {%4,%5,%6,%7}, {%8,%9}, {%0,%1,%2,%3};"
        : "+f"(c[0]), "+f"(c[1]), "+f"(c[2]), "+f"(c[3])
        : "r"(a[0]), "r"(a[1]), "r"(a[2]), "r"(a[3]), "r"(b[0]), "r"(b[1]));
}

__device__ __forceinline__ uint32_t pack_bf(__nv_bfloat16 a, __nv_bfloat16 b) {
    __nv_bfloat162 t; t.x = a; t.y = b;
    uint32_t r; memcpy(&r, &t, 4); return r;
}

// split (x,y) into bf16 hi-pair and lo-pair (residuals)
__device__ __forceinline__ void split2(float x, float y, uint32_t& hi, uint32_t& lo) {
    __nv_bfloat16 hx = __float2bfloat16_rn(x);
    __nv_bfloat16 hy = __float2bfloat16_rn(y);
    __nv_bfloat16 lx = __float2bfloat16_rn(x - __bfloat162float(hx));
    __nv_bfloat16 ly = __float2bfloat16_rn(y - __bfloat162float(hy));
    hi = pack_bf(hx, hy);
    lo = pack_bf(lx, ly);
}

// smem layout: s[row][k2] with k2 XOR-swizzled by (row&7); stride 8 uint32.
__device__ __forceinline__ uint32_t lds_sw(const uint32_t* s, int r, int k2) {
    return s[r * 8 + (k2 ^ (r & 7))];
}
// store an even-based (k2, k2+1) pair with swizzle, as one 8-byte store
__device__ __forceinline__ void sts_pair(uint32_t* s, int m, int k2, uint32_t u0, uint32_t u1) {
    int x = m & 7;
    int p0 = k2 ^ x;
    if (x & 1) { uint32_t t = u0; u0 = u1; u1 = t; }
    *(uint2*)&s[m * 8 + (p0 & ~1)] = make_uint2(u0, u1);
}

// ---------------------------------------------------------------------------
// Tensor-core GEMM, bf16x3 compensated, packed weights, pipelined.
// C[M,N] = A[M,K(lda)] @ Wpacked[K,N]   (K == kpad, multiple of 16)
// BM=128, BN=128, BK=16, 256 threads (8 warps: 4M x 2N), 2 CTAs/SM.
// EPI: 0 = store (no bias); 2 = +bias, relu, red.v2 scatter to g_xout/g_xin.
// ---------------------------------------------------------------------------
template<int EPI>
__global__ __launch_bounds__(256, 2)
void gemm_pk(const float* __restrict__ A,
             const uint32_t* __restrict__ Wh, const uint32_t* __restrict__ Wl,
             const float* __restrict__ bias, float* __restrict__ C,
             int M, int N, int K, int lda, int ldc,
             const int* __restrict__ src, const int* __restrict__ dst)
{
    constexpr int BM = 128, BN = 128;
    __shared__ __align__(16) uint32_t sAh[BM*8], sAl[BM*8], sBh[BN*8], sBl[BN*8];

    const int bm = blockIdx.y * BM, bn = blockIdx.x * BN;
    const int tid = threadIdx.x, wid = tid >> 5, lane = tid & 31;
    const int wm = (wid & 3) * 32, wn = (wid >> 2) * 64;
    const int g = lane >> 2, tig = lane & 3;
    const int wstride = K >> 1;

    // A staging map: thread covers float4 idx = tid and tid+256 (512 total)
    const int am0 = tid >> 2, af = tid & 3;
    const int am1 = 64 + (tid >> 2);
    // W staging map: thread -> (n = tid>>1, part = tid&1), one uint4 per array
    const int wns = tid >> 1, wpart = tid & 1;

    float acc[2][8][4] = {};
    float4 pa0, pa1; uint4 pwh, pwl;

    {   // prologue: tile 0
        int gm0 = bm + am0, gm1 = bm + am1;
        pa0 = (gm0 < M) ? *(const float4*)&A[(size_t)gm0 * lda + af * 4] : make_float4(0,0,0,0);
        pa1 = (gm1 < M) ? *(const float4*)&A[(size_t)gm1 * lda + af * 4] : make_float4(0,0,0,0);
        size_t off = (size_t)(bn + wns) * wstride + wpart * 4;
        pwh = *(const uint4*)&Wh[off];
        pwl = *(const uint4*)&Wl[off];
    }

    const int KT = K >> 4;
    for (int kt = 0; kt < KT; kt++) {
        // ---- stage current tile ----
        {
            uint32_t h0, l0, h1, l1;
            split2(pa0.x, pa0.y, h0, l0);
            split2(pa0.z, pa0.w, h1, l1);
            sts_pair(sAh, am0, af * 2, h0, h1);
            sts_pair(sAl, am0, af * 2, l0, l1);
            split2(pa1.x, pa1.y, h0, l0);
            split2(pa1.z, pa1.w, h1, l1);
            sts_pair(sAh, am1, af * 2, h0, h1);
            sts_pair(sAl, am1, af * 2, l0, l1);
            sts_pair(sBh, wns, wpart * 4 + 0, pwh.x, pwh.y);
            sts_pair(sBh, wns, wpart * 4 + 2, pwh.z, pwh.w);
            sts_pair(sBl, wns, wpart * 4 + 0, pwl.x, pwl.y);
            sts_pair(sBl, wns, wpart * 4 + 2, pwl.z, pwl.w);
        }
        __syncthreads();

        // ---- prefetch next tile ----
        if (kt + 1 < KT) {
            int k0 = (kt + 1) * 16;
            int gm0 = bm + am0, gm1 = bm + am1;
            pa0 = (gm0 < M) ? *(const float4*)&A[(size_t)gm0 * lda + k0 + af * 4] : make_float4(0,0,0,0);
            pa1 = (gm1 < M) ? *(const float4*)&A[(size_t)gm1 * lda + k0 + af * 4] : make_float4(0,0,0,0);
            size_t off = (size_t)(bn + wns) * wstride + (k0 >> 1) + wpart * 4;
            pwh = *(const uint4*)&Wh[off];
            pwl = *(const uint4*)&Wl[off];
        }

        // ---- MMAs ----
        uint32_t ah[2][4], al[2][4];
        #pragma unroll
        for (int mt = 0; mt < 2; mt++) {
            int r0 = wm + mt * 16 + g;
            ah[mt][0] = lds_sw(sAh, r0,     tig);
            ah[mt][1] = lds_sw(sAh, r0 + 8, tig);
            ah[mt][2] = lds_sw(sAh, r0,     tig + 4);
            ah[mt][3] = lds_sw(sAh, r0 + 8, tig + 4);
            al[mt][0] = lds_sw(sAl, r0,     tig);
            al[mt][1] = lds_sw(sAl, r0 + 8, tig);
            al[mt][2] = lds_sw(sAl, r0,     tig + 4);
            al[mt][3] = lds_sw(sAl, r0 + 8, tig + 4);
        }
        #pragma unroll
        for (int nt = 0; nt < 8; nt++) {
            int n = wn + nt * 8 + g;
            uint32_t bh[2], bl[2];
            bh[0] = lds_sw(sBh, n, tig);
            bh[1] = lds_sw(sBh, n, tig + 4);
            bl[0] = lds_sw(sBl, n, tig);
            bl[1] = lds_sw(sBl, n, tig + 4);
            #pragma unroll
            for (int mt = 0; mt < 2; mt++) {
                mma_bf16(acc[mt][nt], ah[mt], bh);
                mma_bf16(acc[mt][nt], al[mt], bh);
                mma_bf16(acc[mt][nt], ah[mt], bl);
            }
        }
        __syncthreads();
    }

    // ---- epilogue ----
    #pragma unroll
    for (int mt = 0; mt < 2; mt++) {
        #pragma unroll
        for (int half = 0; half < 2; half++) {
            int r = bm + wm + mt * 16 + g + half * 8;
            if (r >= M) continue;
            int s = 0, d = 0;
            if (EPI == 2) { s = src[r]; d = dst[r]; }
            #pragma unroll
            for (int nt = 0; nt < 8; nt++) {
                int col0 = bn + wn + nt * 8 + tig * 2;
                float v0 = acc[mt][nt][half * 2 + 0];
                float v1 = acc[mt][nt][half * 2 + 1];
                if (EPI == 2) {
                    v0 = fmaxf(v0 + bias[col0], 0.f);
                    v1 = fmaxf(v1 + bias[col0 + 1], 0.f);
                    red2(&g_xout[(size_t)s * 128 + col0], v0, v1);
                    red2(&g_xin [(size_t)d * 128 + col0], v0, v1);
                } else {
                    *(float2*)&C[(size_t)r * ldc + col0] = make_float2(v0, v1);
                }
            }
        }
    }
}

// ---------------------------------------------------------------------------
// Pack weights into bf16 hi/lo uint32, n-major [n][kpad/2]. One launch.
// ---------------------------------------------------------------------------
__global__ void k_pack(const float* __restrict__ g1wl, const float* __restrict__ g1wr,
                       const float* __restrict__ g1we, const float* __restrict__ g2we,
                       const float* __restrict__ c1w,  const float* __restrict__ g2wl,
                       const float* __restrict__ g2wr, const float* __restrict__ epw)
{
    const float* W; int K, N, n0, kpad; uint32_t *dh, *dl;
    switch (blockIdx.y) {
        case 0: W = g1wl;           K = 258; N = 256; n0 = 0;   kpad = 272; dh = wp_W1h; dl = wp_W1l; break;
        case 1: W = g1wr;           K = 258; N = 256; n0 = 256; kpad = 272; dh = wp_W1h; dl = wp_W1l; break;
        case 2: W = g1we;           K = 64;  N = 256; n0 = 0;   kpad = 64;  dh = wp_Weh; dl = wp_Wel; break;
        case 3: W = g2we;           K = 64;  N = 128; n0 = 256; kpad = 64;  dh = wp_Weh; dl = wp_Wel; break;
        case 4: W = c1w + 256*128;  K = 64;  N = 128; n0 = 384; kpad = 64;  dh = wp_Weh; dl = wp_Wel; break;
        case 5: W = g2wl;           K = 128; N = 128; n0 = 0;   kpad = 128; dh = wp_W2h; dl = wp_W2l; break;
        case 6: W = g2wr;           K = 128; N = 128; n0 = 128; kpad = 128; dh = wp_W2h; dl = wp_W2l; break;
        case 7: W = c1w;            K = 128; N = 128; n0 = 0;   kpad = 128; dh = wp_ABh; dl = wp_ABl; break;
        case 8: W = c1w + 128*128;  K = 128; N = 128; n0 = 128; kpad = 128; dh = wp_ABh; dl = wp_ABl; break;
        default: W = epw;           K = 64;  N = 128; n0 = 0;   kpad = 64;  dh = wp_Ebh; dl = wp_Ebl; break;
    }
    int kh = kpad >> 1;
    int total = N * kh;
    for (int i = blockIdx.x * blockDim.x + threadIdx.x; i < total; i += gridDim.x * blockDim.x) {
        int n = i / kh, k2 = i - n * kh, k = k2 * 2;
        float v0 = (k     < K) ? W[(size_t)k * N + n]       : 0.f;
        float v1 = (k + 1 < K) ? W[(size_t)(k + 1) * N + n] : 0.f;
        uint32_t hi, lo; split2(v0, v1, hi, lo);
        dh[(size_t)(n0 + n) * kh + k2] = hi;
        dl[(size_t)(n0 + n) * kh + k2] = lo;
    }
}

// ---------------------------------------------------------------------------
// Degrees + loop_attr sum. 1 warp / edge.
// ---------------------------------------------------------------------------
__global__ void k_deg_loop(const int* __restrict__ src, const int* __restrict__ dst,
                           const float* __restrict__ ea) {
    int warp = (blockIdx.x * 256 + threadIdx.x) >> 5;
    int lane = threadIdx.x & 31;
    if (warp >= E_) return;
    int s = src[warp], d = dst[warp];
    if (lane == 0) atomicAdd(&g_deg_out[s], 1);
    if (lane == 1) atomicAdd(&g_deg_in[d], 1);
    if (lane < 16) {
        float4 a = reinterpret_cast<const float4*>(ea + (size_t)warp * 64)[lane];
        red4(&g_loop[(size_t)d * 64 + lane * 4], a);
    }
}

// ---------------------------------------------------------------------------
// Build xi (stride 272, pad zeroed); finalize loop_attr.
// ---------------------------------------------------------------------------
__global__ void k_build_xi(const float* __restrict__ node_stats) {
    int n = blockIdx.x;
    int c = threadIdx.x;
    float io = 1.f / fmaxf((float)g_deg_out[n], 1.f);
    float ii = 1.f / fmaxf((float)g_deg_in[n], 1.f);
    g_xi[(size_t)n * 272 + c]       = g_xout[(size_t)n * 128 + c] * io;
    g_xi[(size_t)n * 272 + 128 + c] = g_xin [(size_t)n * 128 + c] * ii;
    if (c < 2)       g_xi[(size_t)n * 272 + 256 + c] = node_stats[(size_t)n * 2 + c];
    else if (c < 16) g_xi[(size_t)n * 272 + 256 + c] = 0.f;
    if (c < 64) g_loop[(size_t)n * 64 + c] *= ii;
}

// ---------------------------------------------------------------------------
// Fused GATv2 attention (no max shift). 1 warp / edge.
// x: xl at row*xstr, xr at row*xstr + xroff. ew strided.
// ---------------------------------------------------------------------------
template<int H>
__global__ void k_attn(const float* __restrict__ x, int xstr, int xroff,
                       const float* __restrict__ ewE, int ewstr,
                       const float* __restrict__ ewL, int ewLstr,
                       const float* __restrict__ att,
                       const int* __restrict__ src, const int* __restrict__ dst,
                       float* __restrict__ den, float* __restrict__ osum)
{
    const int CH = H * 128;
    __shared__ float satt[CH];
    if (threadIdx.x < CH) satt[threadIdx.x] = att[threadIdx.x];
    __syncthreads();
    int warp = (blockIdx.x * 256 + threadIdx.x) >> 5;
    int lane = threadIdx.x & 31;
    if (warp >= E2_) return;
    int s, d; const float* ew;
    if (warp < E_) { s = src[warp]; d = dst[warp]; ew = ewE + (size_t)warp * ewstr; }
    else           { s = d = warp - E_;            ew = ewL + (size_t)s * ewLstr; }
    const float* pl = x + (size_t)s * xstr;
    const float* pr = x + (size_t)d * xstr + xroff;

    float4 xlv[H];
    float lg[H];
    #pragma unroll
    for (int h = 0; h < H; h++) {
        int off = h * 128 + lane * 4;
        float4 l4 = *(const float4*)&pl[off];
        float4 r4 = *(const float4*)&pr[off];
        float4 e4 = *(const float4*)&ew[off];
        float4 a4 = *(const float4*)&satt[off];
        xlv[h] = l4;
        float v0 = l4.x + r4.x + e4.x; v0 = (v0 > 0.f) ? v0 : 0.2f * v0;
        float v1 = l4.y + r4.y + e4.y; v1 = (v1 > 0.f) ? v1 : 0.2f * v1;
        float v2 = l4.z + r4.z + e4.z; v2 = (v2 > 0.f) ? v2 : 0.2f * v2;
        float v3 = l4.w + r4.w + e4.w; v3 = (v3 > 0.f) ? v3 : 0.2f * v3;
        lg[h] = v0 * a4.x + v1 * a4.y + v2 * a4.z + v3 * a4.w;
    }
    #pragma unroll
    for (int h = 0; h < H; h++)
        #pragma unroll
        for (int o = 16; o > 0; o >>= 1)
            lg[h] += __shfl_xor_sync(0xffffffffu, lg[h], o);
    float a[H];
    #pragma unroll
    for (int h = 0; h < H; h++) a[h] = expf(lg[h]);
    if (lane == 0) {
        #pragma unroll
        for (int h = 0; h < H; h++) atomicAdd(&den[(size_t)d * H + h], a[h]);
    }
    #pragma unroll
    for (int h = 0; h < H; h++) {
        float4 v = xlv[h];
        v.x *= a[h]; v.y *= a[h]; v.z *= a[h]; v.w *= a[h];
        red4(&osum[((size_t)d * H + h) * 128 + lane * 4], v);
    }
}

// ---------------------------------------------------------------------------
// Node finalize: head mean + bias, layernorm, elu. 1 warp / node.
// ---------------------------------------------------------------------------
template<int H>
__global__ void k_node(const float* __restrict__ osum, const float* __restrict__ den,
                       const float* __restrict__ bias,
                       const float* __restrict__ lng, const float* __restrict__ lnb,
                       float* __restrict__ out)
{
    int warp = (blockIdx.x * 256 + threadIdx.x) >> 5;
    int lane = threadIdx.x & 31;
    if (warp >= N_) return;
    int n = warp;
    float dinv[H];
    #pragma unroll
    for (int h = 0; h < H; h++)
        dinv[h] = 1.f / fmaxf(den[(size_t)n * H + h], 1e-16f);
    float v[4];
    float sum = 0.f;
    #pragma unroll
    for (int i = 0; i < 4; i++) {
        int c = i * 32 + lane;
        float o = 0.f;
        #pragma unroll
        for (int h = 0; h < H; h++)
            o += osum[((size_t)n * H + h) * 128 + c] * dinv[h];
        o = o * (1.f / H) + bias[c];
        v[i] = o;
        sum += o;
    }
    #pragma unroll
    for (int o = 16; o > 0; o >>= 1) sum += __shfl_xor_sync(0xffffffffu, sum, o);
    float mu = sum * (1.f / 128.f);
    float var = 0.f;
    #pragma unroll
    for (int i = 0; i < 4; i++) { float t = v[i] - mu; var += t * t; }
    #pragma unroll
    for (int o = 16; o > 0; o >>= 1) var += __shfl_xor_sync(0xffffffffu, var, o);
    var *= (1.f / 128.f);
    float rs = rsqrtf(var + 1e-5f);
    #pragma unroll
    for (int i = 0; i < 4; i++) {
        int c = i * 32 + lane;
        float hn = (v[i] - mu) * rs * lng[c] + lnb[c];
        hn = (hn > 0.f) ? hn : expm1f(hn);
        out[(size_t)n * 128 + c] = hn;
    }
}

// ---------------------------------------------------------------------------
// Fused classifier: per-edge h = relu(A[src]+B[dst]+Cea+c1b) in smem,
// tensor-core h@c2w (K=128 -> N=64), epilogue relu + dot c3w, row-reduce.
// ---------------------------------------------------------------------------
__global__ void k_classifier(const int* __restrict__ src, const int* __restrict__ dst,
                             const float* __restrict__ c1b, const float* __restrict__ c2w,
                             const float* __restrict__ c2b, const float* __restrict__ c3w,
                             const float* __restrict__ c3b, float* __restrict__ out)
{
    constexpr int BM = 128, BN = 64, BK = 16, PAD = 20, K = 128;
    __shared__ __nv_bfloat16 Ah[BM * PAD], Al[BM * PAD];
    __shared__ __nv_bfloat16 Bh[BN * PAD], Bl[BN * PAD];
    __shared__ int ssrc[BM], sdst[BM];
    __shared__ float rowsum[BM];

    const int bm = blockIdx.x * BM;
    const int tid = threadIdx.x, wid = tid >> 5, lane = tid & 31;
    const int wm = (wid & 3) * 32;
    const int wn = (wid >> 2) * 32;
    const int g = lane >> 2, tig = lane & 3;

    if (tid < BM) {
        ssrc[tid] = src[bm + tid];
        sdst[tid] = dst[bm + tid];
        rowsum[tid] = 0.f;
    }
    __syncthreads();

    float acc[2][4][4] = {};

    for (int k0 = 0; k0 < K; k0 += BK) {
        #pragma unroll
        for (int i = 0; i < 8; i++) {
            int idx = tid + i * 256;
            int m = idx >> 4, k = idx & 15;
            int e = bm + m, gk = k0 + k;
            float v = g_AB[(size_t)ssrc[m] * 256 + gk]
                    + g_AB[(size_t)sdst[m] * 256 + 128 + gk]
                    + g_ew[(size_t)e * 512 + 384 + gk] + c1b[gk];
            v = fmaxf(v, 0.f);
            __nv_bfloat16 h = __float2bfloat16_rn(v);
            Ah[m * PAD + k] = h;
            Al[m * PAD + k] = __float2bfloat16_rn(v - __bfloat162float(h));
        }
        #pragma unroll
        for (int i = 0; i < 4; i++) {
            int idx = tid + i * 256;
            int k = idx >> 6, n = idx & 63;
            float v = c2w[(size_t)(k0 + k) * 64 + n];
            __nv_bfloat16 h = __float2bfloat16_rn(v);
            Bh[n * PAD + k] = h;
            Bl[n * PAD + k] = __float2bfloat16_rn(v - __bfloat162float(h));
        }
        __syncthreads();

        uint32_t bh[4][2], bl[4][2];
        #pragma unroll
        for (int nt = 0; nt < 4; nt++) {
            int n = wn + nt * 8 + g;
            bh[nt][0] = *(const uint32_t*)&Bh[n * PAD + tig * 2];
            bh[nt][1] = *(const uint32_t*)&Bh[n * PAD + tig * 2 + 8];
            bl[nt][0] = *(const uint32_t*)&Bl[n * PAD + tig * 2];
            bl[nt][1] = *(const uint32_t*)&Bl[n * PAD + tig * 2 + 8];
        }
        #pragma unroll
        for (int mt = 0; mt < 2; mt++) {
            int r0 = wm + mt * 16 + g;
            uint32_t ah[4], al[4];
            ah[0] = *(const uint32_t*)&Ah[r0 * PAD + tig * 2];
            ah[1] = *(const uint32_t*)&Ah[(r0 + 8) * PAD + tig * 2];
            ah[2] = *(const uint32_t*)&Ah[r0 * PAD + tig * 2 + 8];
            ah[3] = *(const uint32_t*)&Ah[(r0 + 8) * PAD + tig * 2 + 8];
            al[0] = *(const uint32_t*)&Al[r0 * PAD + tig * 2];
            al[1] = *(const uint32_t*)&Al[(r0 + 8) * PAD + tig * 2];
            al[2] = *(const uint32_t*)&Al[r0 * PAD + tig * 2 + 8];
            al[3] = *(const uint32_t*)&Al[(r0 + 8) * PAD + tig * 2 + 8];
            #pragma unroll
            for (int nt = 0; nt < 4; nt++) {
                mma_bf16(acc[mt][nt], ah, bh[nt]);
                mma_bf16(acc[mt][nt], al, bh[nt]);
                mma_bf16(acc[mt][nt], ah, bl[nt]);
            }
        }
        __syncthreads();
    }

    #pragma unroll
    for (int mt = 0; mt < 2; mt++) {
        #pragma unroll
        for (int half = 0; half < 2; half++) {
            int r = wm + mt * 16 + g + half * 8;
            float p = 0.f;
            #pragma unroll
            for (int nt = 0; nt < 4; nt++) {
                int col = wn + nt * 8 + tig * 2;
                float t0 = fmaxf(acc[mt][nt][half * 2 + 0] + c2b[col], 0.f);
                float t1 = fmaxf(acc[mt][nt][half * 2 + 1] + c2b[col + 1], 0.f);
                p += t0 * c3w[col] + t1 * c3w[col + 1];
            }
            atomicAdd(&rowsum[r], p);
        }
    }
    __syncthreads();
    if (tid < BM) out[bm + tid] = rowsum[tid] + c3b[0];
}

// ---------------------------------------------------------------------------
// Host launch
// ---------------------------------------------------------------------------
static void* sym(const void* s) { void* p = nullptr; cudaGetSymbolAddress(&p, s); return p; }

static inline dim3 ggrid(int M, int N) { return dim3((N + 127) / 128, (M + 127) / 128); }

extern "C" void kernel_launch(void* const* d_in, const int* in_sizes, int n_in,
                              void* d_out, int out_size)
{
    const float* node_stats = (const float*)d_in[1];
    const int*   edge_index = (const int*)  d_in[2];
    const float* edge_attr  = (const float*)d_in[3];
    const float* epw  = (const float*)d_in[4];
    const float* epb  = (const float*)d_in[5];
    const float* g1wl = (const float*)d_in[6];
    const float* g1wr = (const float*)d_in[7];
    const float* g1we = (const float*)d_in[8];
    const float* g1att= (const float*)d_in[9];
    const float* g1b  = (const float*)d_in[10];
    const float* n1g  = (const float*)d_in[11];
    const float* n1b  = (const float*)d_in[12];
    const float* g2wl = (const float*)d_in[13];
    const float* g2wr = (const float*)d_in[14];
    const float* g2we = (const float*)d_in[15];
    const float* g2att= (const float*)d_in[16];
    const float* g2b  = (const float*)d_in[17];
    const float* n2g  = (const float*)d_in[18];
    const float* n2b  = (const float*)d_in[19];
    const float* c1w  = (const float*)d_in[20];
    const float* c1b  = (const float*)d_in[21];
    const float* c2w  = (const float*)d_in[22];
    const float* c2b  = (const float*)d_in[23];
    const float* c3w  = (const float*)d_in[24];
    const float* c3b  = (const float*)d_in[25];

    const int* src = edge_index;
    const int* dst = edge_index + E_;
    float* out = (float*)d_out;

    float* p_xi   = (float*)sym(g_xi);
    float* p_loop = (float*)sym(g_loop);
    float* p_x1   = (float*)sym(g_x1);
    float* p_ew   = (float*)sym(g_ew);
    float* p_ewL  = (float*)sym(g_ewL);
    float* p_den1 = (float*)sym(g_den1);
    float* p_os1  = (float*)sym(g_osum1);
    float* p_h1   = (float*)sym(g_h1);
    float* p_x2   = (float*)sym(g_x2);
    float* p_den2 = (float*)sym(g_den2);
    float* p_os2  = (float*)sym(g_osum2);
    float* p_h2   = (float*)sym(g_h2);
    float* p_AB   = (float*)sym(g_AB);

    const uint32_t* p_W1h = (const uint32_t*)sym(wp_W1h);
    const uint32_t* p_W1l = (const uint32_t*)sym(wp_W1l);
    const uint32_t* p_Weh = (const uint32_t*)sym(wp_Weh);
    const uint32_t* p_Wel = (const uint32_t*)sym(wp_Wel);
    const uint32_t* p_W2h = (const uint32_t*)sym(wp_W2h);
    const uint32_t* p_W2l = (const uint32_t*)sym(wp_W2l);
    const uint32_t* p_ABh = (const uint32_t*)sym(wp_ABh);
    const uint32_t* p_ABl = (const uint32_t*)sym(wp_ABl);
    const uint32_t* p_Ebh = (const uint32_t*)sym(wp_Ebh);
    const uint32_t* p_Ebl = (const uint32_t*)sym(wp_Ebl);

    // ---- zero accumulators ----
    cudaMemsetAsync(sym(g_deg_out), 0, (size_t)N_ * 4);
    cudaMemsetAsync(sym(g_deg_in),  0, (size_t)N_ * 4);
    cudaMemsetAsync(sym(g_xout),    0, (size_t)N_ * 128 * 4);
    cudaMemsetAsync(sym(g_xin),     0, (size_t)N_ * 128 * 4);
    cudaMemsetAsync(p_loop,         0, (size_t)N_ * 64 * 4);
    cudaMemsetAsync(p_den1,         0, (size_t)N_ * 2 * 4);
    cudaMemsetAsync(p_os1,          0, (size_t)N_ * 256 * 4);
    cudaMemsetAsync(p_den2,         0, (size_t)N_ * 4);
    cudaMemsetAsync(p_os2,          0, (size_t)N_ * 128 * 4);

    // ---- weight packing (once per replay; cheap) ----
    k_pack<<<dim3(144, 10), 256>>>(g1wl, g1wr, g1we, g2we, c1w, g2wl, g2wr, epw);

    // ---- phase 1: degrees, loop sums, emb GEMM fused with scatter ----
    k_deg_loop<<<(E_ + 7) / 8, 256>>>(src, dst, edge_attr);
    gemm_pk<2><<<ggrid(E_, 128), 256>>>(edge_attr, p_Ebh, p_Ebl, epb, nullptr,
                                        E_, 128, 64, 64, 0, src, dst);
    k_build_xi<<<N_, 128>>>(node_stats);

    // ---- combined GEMMs ----
    gemm_pk<0><<<ggrid(N_, 512), 256>>>(p_xi, p_W1h, p_W1l, nullptr, p_x1,
                                        N_, 512, 272, 272, 512, nullptr, nullptr);
    gemm_pk<0><<<ggrid(E_, 512), 256>>>(edge_attr, p_Weh, p_Wel, nullptr, p_ew,
                                        E_, 512, 64, 64, 512, nullptr, nullptr);
    gemm_pk<0><<<ggrid(N_, 384), 256>>>(p_loop, p_Weh, p_Wel, nullptr, p_ewL,
                                        N_, 384, 64, 64, 384, nullptr, nullptr);

    // ---- GAT layer 1 (heads=2) ----
    k_attn<2><<<(E2_ + 7) / 8, 256>>>(p_x1, 512, 256, p_ew, 512, p_ewL, 384,
                                      g1att, src, dst, p_den1, p_os1);
    k_node<2><<<(N_ + 7) / 8, 256>>>(p_os1, p_den1, g1b, n1g, n1b, p_h1);

    // ---- GAT layer 2 (heads=1) ----
    gemm_pk<0><<<ggrid(N_, 256), 256>>>(p_h1, p_W2h, p_W2l, nullptr, p_x2,
                                        N_, 256, 128, 128, 256, nullptr, nullptr);
    k_attn<1><<<(E2_ + 7) / 8, 256>>>(p_x2, 256, 128, p_ew + 256, 512, p_ewL + 256, 384,
                                      g2att, src, dst, p_den2, p_os2);
    k_node<1><<<(N_ + 7) / 8, 256>>>(p_os2, p_den2, g2b, n2g, n2b, p_h2);

    // ---- classifier ----
    gemm_pk<0><<<ggrid(N_, 256), 256>>>(p_h2, p_ABh, p_ABl, nullptr, p_AB,
                                        N_, 256, 128, 128, 256, nullptr, nullptr);
    k_classifier<<<E_ / 128, 256>>>(src, dst, c1b, c2w, c2b, c3w, c3b, out);
}